// round 12
// baseline (speedup 1.0000x reference)
#include <cuda_runtime.h>
#include <cuda_bf16.h>
#include <cstdint>

#define BATCH 8
#define NSEQ  2048
#define CDIM  512

// ---------------------------------------------------------------------------
// Scratch (__device__ globals per allocation-free rule)
// ---------------------------------------------------------------------------
__device__ __align__(16) __nv_bfloat16 g_fb[BATCH * NSEQ * CDIM];      // feat bf16
__device__ __align__(16) __nv_bfloat16 g_wb[3 * CDIM * CDIM];          // wq,wk,wv bf16
__device__ __align__(16) __nv_bfloat16 g_qb[BATCH * NSEQ * CDIM];
__device__ __align__(16) __nv_bfloat16 g_kb[BATCH * NSEQ * CDIM];
__device__ __align__(16) __nv_bfloat16 g_vb[BATCH * NSEQ * CDIM];      // natural [m][d]
__device__ __align__(16) __nv_bfloat16 g_s[(size_t)BATCH * NSEQ * NSEQ];  // exp(S-30)
// 32 partial sums per row: 16 col-blocks x 2 n-warps.
__device__ __align__(16) float g_spart[BATCH * NSEQ * 32];

// ---------------------------------------------------------------------------
// Helpers
// ---------------------------------------------------------------------------
__device__ __forceinline__ uint32_t smem_to_u32(const void* p) {
    uint32_t a;
    asm("{ .reg .u64 t; cvta.to.shared.u64 t, %1; cvt.u32.u64 %0, t; }" : "=r"(a) : "l"(p));
    return a;
}

__device__ __forceinline__ void cp_async16(uint32_t saddr, const void* gptr) {
    asm volatile("cp.async.cg.shared.global [%0], [%1], 16;" :: "r"(saddr), "l"(gptr));
}
#define CP_COMMIT() asm volatile("cp.async.commit_group;" ::: "memory")
#define CP_WAIT0()  asm volatile("cp.async.wait_group 0;" ::: "memory")

__device__ __forceinline__ void ldsm4(uint32_t r[4], uint32_t addr) {
    asm volatile("ldmatrix.sync.aligned.m8n8.x4.shared.b16 {%0,%1,%2,%3}, [%4];"
        : "=r"(r[0]), "=r"(r[1]), "=r"(r[2]), "=r"(r[3]) : "r"(addr));
}
__device__ __forceinline__ void ldsm4t(uint32_t r[4], uint32_t addr) {
    asm volatile("ldmatrix.sync.aligned.m8n8.x4.trans.shared.b16 {%0,%1,%2,%3}, [%4];"
        : "=r"(r[0]), "=r"(r[1]), "=r"(r[2]), "=r"(r[3]) : "r"(addr));
}

__device__ __forceinline__ void mma_bf16(float c[4], const uint32_t a[4], const uint32_t b[2]) {
    asm volatile(
        "mma.sync.aligned.m16n8k16.row.col.f32.bf16.bf16.f32 "
        "{%0,%1,%2,%3}, {%4,%5,%6,%7}, {%8,%9}, {%0,%1,%2,%3};"
        : "+f"(c[0]), "+f"(c[1]), "+f"(c[2]), "+f"(c[3])
        : "r"(a[0]), "r"(a[1]), "r"(a[2]), "r"(a[3]), "r"(b[0]), "r"(b[1]));
}

__device__ __forceinline__ uint32_t packbf(float x, float y) {
    __nv_bfloat162 h = __floats2bfloat162_rn(x, y);
    return *reinterpret_cast<uint32_t*>(&h);
}

// ---------------------------------------------------------------------------
// SMEM tile layouts (bf16, padded rows so ldmatrix 16B units hit distinct banks)
//   NT tile: 128 rows x 64 k-bf16, row stride 72 bf16 = 144 B -> 18432 B
//   NN tile:  64 k-rows x 128 n-bf16, row stride 136 bf16 = 272 B -> 17408 B
// ---------------------------------------------------------------------------
#define NT_TILE_B 18432
#define NN_TILE_B 17408

__device__ __forceinline__ void load_ntb(const __nv_bfloat16* __restrict__ g, long ld,
                                         int rowBase, int kt, uint32_t sbase, int tid) {
    #pragma unroll
    for (int i = 0; i < 4; i++) {
        int idx = i * 256 + tid;      // 1024 chunks of 16B
        int r = idx >> 3, f8 = idx & 7;
        cp_async16(sbase + (uint32_t)(r * 144 + f8 * 16),
                   g + (long)(rowBase + r) * ld + kt + f8 * 8);
    }
}

__device__ __forceinline__ void load_nnb(const __nv_bfloat16* __restrict__ g, long ld,
                                         int colBase, int kt, uint32_t sbase, int tid) {
    #pragma unroll
    for (int i = 0; i < 4; i++) {
        int idx = i * 256 + tid;
        int r = idx >> 4, c8 = idx & 15;
        cp_async16(sbase + (uint32_t)(r * 272 + c8 * 16),
                   g + (long)(kt + r) * ld + colBase + c8 * 8);
    }
}

// One 64-k slab, warp tile 32x64. A from NT tile; B NT (BNN=0) or NN+trans (BNN=1).
template<int BNN>
__device__ __forceinline__ void slab_bf16(uint32_t aBase, uint32_t bBase,
                                          float acc[2][8][4], int m0, int n0, int lane) {
    uint32_t aOff[2], bOff[4];
    #pragma unroll
    for (int mt = 0; mt < 2; mt++)
        aOff[mt] = (uint32_t)((m0 + mt * 16 + (lane & 15)) * 144 + ((lane & 16) ? 16 : 0));
    #pragma unroll
    for (int nt2 = 0; nt2 < 4; nt2++) {
        if (BNN)
            bOff[nt2] = (uint32_t)(((lane & 7) + ((lane & 8) ? 8 : 0)) * 272
                        + (n0 + nt2 * 16) * 2 + ((lane & 16) ? 16 : 0));
        else
            bOff[nt2] = (uint32_t)((n0 + nt2 * 16 + (lane & 7) + ((lane & 16) ? 8 : 0)) * 144
                        + ((lane & 8) ? 16 : 0));
    }
    #pragma unroll
    for (int kk = 0; kk < 4; kk++) {
        uint32_t a[2][4];
        ldsm4(a[0], aBase + aOff[0] + kk * 32);
        ldsm4(a[1], aBase + aOff[1] + kk * 32);
        uint32_t b[4][4];
        #pragma unroll
        for (int nt2 = 0; nt2 < 4; nt2++) {
            if (BNN) ldsm4t(b[nt2], bBase + bOff[nt2] + kk * 16 * 272);
            else     ldsm4 (b[nt2], bBase + bOff[nt2] + kk * 32);
        }
        #pragma unroll
        for (int mt = 0; mt < 2; mt++)
            #pragma unroll
            for (int nt2 = 0; nt2 < 4; nt2++) {
                mma_bf16(acc[mt][nt2 * 2 + 0], a[mt], &b[nt2][0]);
                mma_bf16(acc[mt][nt2 * 2 + 1], a[mt], &b[nt2][2]);
            }
    }
}

// ---------------------------------------------------------------------------
// Combined convert kernel (f32 -> bf16): feat (2,097,152 float4s) then the
// three weight matrices (3 x 65,536 float4s). One launch.
// ---------------------------------------------------------------------------
#define FEAT_F4 (BATCH * NSEQ * CDIM / 4)          // 2097152
#define W_F4    (CDIM * CDIM / 4)                  // 65536
#define CONV_BLOCKS ((FEAT_F4 + 3 * W_F4) / 256)   // 8960

__global__ __launch_bounds__(256) void conv_all(const float4* __restrict__ feat,
                                                const float4* __restrict__ wq,
                                                const float4* __restrict__ wk,
                                                const float4* __restrict__ wv) {
    int idx = blockIdx.x * 256 + threadIdx.x;
    const float4* src;
    uint2* dst;
    int off;
    if (idx < FEAT_F4) {
        src = feat;             dst = (uint2*)g_fb; off = idx;
    } else if (idx < FEAT_F4 + W_F4) {
        src = wq;  dst = (uint2*)g_wb;              off = idx - FEAT_F4;
    } else if (idx < FEAT_F4 + 2 * W_F4) {
        src = wk;  dst = (uint2*)g_wb + W_F4;       off = idx - FEAT_F4 - W_F4;
    } else {
        src = wv;  dst = (uint2*)g_wb + 2 * W_F4;   off = idx - FEAT_F4 - 2 * W_F4;
    }
    float4 v = src[off];
    uint2 o;
    o.x = packbf(v.x, v.y);
    o.y = packbf(v.z, v.w);
    dst[off] = o;
}

// ---------------------------------------------------------------------------
// Kernel 1: QKV projections (NT). CTA 128x128, 256 thr, 2-stage pipeline.
// M=16384, N=512, K=512
// ---------------------------------------------------------------------------
__global__ __launch_bounds__(256, 2) void qkv_bf16(
    const float* __restrict__ bq, const float* __restrict__ bk,
    const float* __restrict__ bv)
{
    extern __shared__ char sm[];
    uint32_t sb = smem_to_u32(sm);
    const int tid = threadIdx.x;
    const int wid = tid >> 5, lane = tid & 31;
    const int lq = lane >> 2, lr = lane & 3;
    const int m0 = (wid >> 1) * 32, n0 = (wid & 1) * 64;
    const int z = blockIdx.z;
    const __nv_bfloat16* W = g_wb + (long)z * CDIM * CDIM;
    const float* bias = (z == 0) ? bq : (z == 1) ? bk : bv;
    __nv_bfloat16* out = (z == 0) ? g_qb : (z == 1) ? g_kb : g_vb;

    const int rowBase = blockIdx.y * 128;
    const int colBase = blockIdx.x * 128;

    uint32_t aAddr[2] = { sb, sb + NT_TILE_B };
    uint32_t bAddr[2] = { sb + 2 * NT_TILE_B, sb + 3 * NT_TILE_B };

    float acc[2][8][4] = {};

    load_ntb(g_fb, CDIM, rowBase, 0, aAddr[0], tid);
    load_ntb(W,    CDIM, colBase, 0, bAddr[0], tid);
    CP_COMMIT(); CP_WAIT0();
    __syncthreads();

    const int nslab = CDIM / 64;
    for (int s = 0; s < nslab; s++) {
        int cur = s & 1;
        if (s + 1 < nslab) {
            int nxt = cur ^ 1;
            load_ntb(g_fb, CDIM, rowBase, (s + 1) * 64, aAddr[nxt], tid);
            load_ntb(W,    CDIM, colBase, (s + 1) * 64, bAddr[nxt], tid);
            CP_COMMIT();
        }
        slab_bf16<0>(aAddr[cur], bAddr[cur], acc, m0, n0, lane);
        if (s + 1 < nslab) CP_WAIT0();
        __syncthreads();
    }

    #pragma unroll
    for (int mt = 0; mt < 2; mt++)
        #pragma unroll
        for (int half = 0; half < 2; half++) {
            int row = rowBase + m0 + mt * 16 + lq + half * 8;
            #pragma unroll
            for (int nt = 0; nt < 8; nt++) {
                int col = colBase + n0 + nt * 8 + lr * 2;
                uint32_t p = packbf(acc[mt][nt][half * 2 + 0] + bias[col + 0],
                                    acc[mt][nt][half * 2 + 1] + bias[col + 1]);
                *(uint32_t*)&out[(long)row * CDIM + col] = p;
            }
        }
}

// ---------------------------------------------------------------------------
// Kernel 2: scores for ONE batch (bz argument). CTA 128x128. Writes exp(S-30)
// in bf16, plus one partial row-sum per (row, 64-col warp span).
// ---------------------------------------------------------------------------
__global__ __launch_bounds__(256, 2) void scores_bf16(int bz)
{
    extern __shared__ char sm[];
    uint32_t sb = smem_to_u32(sm);
    const int tid = threadIdx.x;
    const int wid = tid >> 5, lane = tid & 31;
    const int lq = lane >> 2, lr = lane & 3;
    const int m0 = (wid >> 1) * 32, n0 = (wid & 1) * 64;

    const __nv_bfloat16* Aq = g_qb + (long)bz * NSEQ * CDIM;
    const __nv_bfloat16* Bk = g_kb + (long)bz * NSEQ * CDIM;
    __nv_bfloat16* out = g_s + (size_t)bz * NSEQ * NSEQ;
    const int rowBase = blockIdx.y * 128;
    const int colBase = blockIdx.x * 128;

    uint32_t aAddr[2] = { sb, sb + NT_TILE_B };
    uint32_t bAddr[2] = { sb + 2 * NT_TILE_B, sb + 3 * NT_TILE_B };

    float acc[2][8][4] = {};

    load_ntb(Aq, CDIM, rowBase, 0, aAddr[0], tid);
    load_ntb(Bk, CDIM, colBase, 0, bAddr[0], tid);
    CP_COMMIT(); CP_WAIT0();
    __syncthreads();

    const int nslab = CDIM / 64;
    for (int s = 0; s < nslab; s++) {
        int cur = s & 1;
        if (s + 1 < nslab) {
            int nxt = cur ^ 1;
            load_ntb(Aq, CDIM, rowBase, (s + 1) * 64, aAddr[nxt], tid);
            load_ntb(Bk, CDIM, colBase, (s + 1) * 64, bAddr[nxt], tid);
            CP_COMMIT();
        }
        slab_bf16<0>(aAddr[cur], bAddr[cur], acc, m0, n0, lane);
        if (s + 1 < nslab) CP_WAIT0();
        __syncthreads();
    }

    // Epilogue: exp(s - 30) (unnormalized softmax numerator; constant offset
    // cancels in pv's normalize) + per-row partial sums via lr-quad reduce.
    #pragma unroll
    for (int mt = 0; mt < 2; mt++)
        #pragma unroll
        for (int half = 0; half < 2; half++) {
            int row = rowBase + m0 + mt * 16 + lq + half * 8;
            float rp = 0.f;
            #pragma unroll
            for (int nt = 0; nt < 8; nt++) {
                int col = colBase + n0 + nt * 8 + lr * 2;
                float e0 = __expf(acc[mt][nt][half * 2 + 0] - 30.0f);
                float e1 = __expf(acc[mt][nt][half * 2 + 1] - 30.0f);
                rp += e0 + e1;
                *(uint32_t*)&out[(size_t)row * NSEQ + col] = packbf(e0, e1);
            }
            // Lanes lq*4 + {0..3} hold the same row; combine their spans.
            rp += __shfl_xor_sync(0xffffffffu, rp, 1);
            rp += __shfl_xor_sync(0xffffffffu, rp, 2);
            if (lr == 0) {
                int part = blockIdx.x * 2 + (n0 >> 6);   // 0..31, unique per warp
                g_spart[((size_t)(bz * NSEQ) + row) * 32 + part] = rp;
            }
        }
}

// ---------------------------------------------------------------------------
// Kernel 3: PV + residual + normalize for ONE batch (bz argument). CTA
// 128x128, 2-stage. A = exp(S), B = V [m][d] via trans ldmatrix.
// out = feat + acc * (1/sqrt(C)) / rowsum (rowsum from g_spart partials).
// ---------------------------------------------------------------------------
__global__ __launch_bounds__(256, 2) void pv_bf16(const float* __restrict__ feat,
                                                  float* __restrict__ out, int bz)
{
    extern __shared__ char sm[];
    uint32_t sb = smem_to_u32(sm);
    const int tid = threadIdx.x;
    const int wid = tid >> 5, lane = tid & 31;
    const int lq = lane >> 2, lr = lane & 3;
    const int m0 = (wid >> 1) * 32, n0 = (wid & 1) * 64;

    const __nv_bfloat16* Ap = g_s + (size_t)bz * NSEQ * NSEQ;
    const __nv_bfloat16* Bv = g_vb + (long)bz * NSEQ * CDIM;
    const int rowBase = blockIdx.y * 128;
    const int colBase = blockIdx.x * 128;

    uint32_t aAddr[2] = { sb, sb + NT_TILE_B };
    uint32_t bAddr[2] = { sb + 2 * NT_TILE_B, sb + 2 * NT_TILE_B + NN_TILE_B };

    float acc[2][8][4] = {};

    load_ntb(Ap, NSEQ, rowBase, 0, aAddr[0], tid);
    load_nnb(Bv, CDIM, colBase, 0, bAddr[0], tid);
    CP_COMMIT(); CP_WAIT0();
    __syncthreads();

    const int nslab = NSEQ / 64;
    for (int s = 0; s < nslab; s++) {
        int cur = s & 1;
        if (s + 1 < nslab) {
            int nxt = cur ^ 1;
            load_ntb(Ap, NSEQ, rowBase, (s + 1) * 64, aAddr[nxt], tid);
            load_nnb(Bv, CDIM, colBase, (s + 1) * 64, bAddr[nxt], tid);
            CP_COMMIT();
        }
        slab_bf16<1>(aAddr[cur], bAddr[cur], acc, m0, n0, lane);
        if (s + 1 < nslab) CP_WAIT0();
        __syncthreads();
    }

    // Gather row normalizers: 32 partials per row -> smem (reuses tile smem;
    // the mainloop's final __syncthreads has retired all tile reads).
    float* rsh = (float*)sm;
    if (tid < 128) {
        const float4* p = (const float4*)(g_spart + ((size_t)(bz * NSEQ) + rowBase + tid) * 32);
        float ssum = 0.f;
        #pragma unroll
        for (int i = 0; i < 8; i++) {
            float4 v = p[i];
            ssum += (v.x + v.y) + (v.z + v.w);
        }
        rsh[tid] = 0.044194173824159216f / ssum;   // (1/sqrt(512)) / rowsum
    }
    __syncthreads();

    #pragma unroll
    for (int mt = 0; mt < 2; mt++)
        #pragma unroll
        for (int half = 0; half < 2; half++) {
            int rloc = m0 + mt * 16 + lq + half * 8;
            long gRow = (long)bz * NSEQ + rowBase + rloc;
            const float nrm = rsh[rloc];
            #pragma unroll
            for (int nt = 0; nt < 8; nt++) {
                int col = colBase + n0 + nt * 8 + lr * 2;
                float2 f = *(const float2*)&feat[gRow * CDIM + col];
                float2 o;
                o.x = fmaf(acc[mt][nt][half * 2 + 0], nrm, f.x);
                o.y = fmaf(acc[mt][nt][half * 2 + 1], nrm, f.y);
                *(float2*)&out[gRow * CDIM + col] = o;
            }
        }
}

// ---------------------------------------------------------------------------
#define SMEM_NT_BYTES (4 * NT_TILE_B)                 // 73728
#define SMEM_PV_BYTES (2 * NT_TILE_B + 2 * NN_TILE_B) // 71680

extern "C" void kernel_launch(void* const* d_in, const int* in_sizes, int n_in,
                              void* d_out, int out_size)
{
    const float* feat = (const float*)d_in[0];
    const float* wq   = (const float*)d_in[1];
    const float* bq   = (const float*)d_in[2];
    const float* wk   = (const float*)d_in[3];
    const float* bk   = (const float*)d_in[4];
    const float* wv   = (const float*)d_in[5];
    const float* bv   = (const float*)d_in[6];
    float* out = (float*)d_out;

    // One-time host-object setup (no device memory involved). Created on the
    // first (non-captured correctness) call; reused during graph capture.
    static cudaStream_t s1 = nullptr;
    static cudaEvent_t evb[BATCH], evj;
    if (!s1) {
        cudaStreamCreateWithFlags(&s1, cudaStreamNonBlocking);
        for (int b = 0; b < BATCH; b++)
            cudaEventCreateWithFlags(&evb[b], cudaEventDisableTiming);
        cudaEventCreateWithFlags(&evj, cudaEventDisableTiming);
        cudaFuncSetAttribute(qkv_bf16,    cudaFuncAttributeMaxDynamicSharedMemorySize, SMEM_NT_BYTES);
        cudaFuncSetAttribute(scores_bf16, cudaFuncAttributeMaxDynamicSharedMemorySize, SMEM_NT_BYTES);
        cudaFuncSetAttribute(pv_bf16,     cudaFuncAttributeMaxDynamicSharedMemorySize, SMEM_PV_BYTES);
    }

    // Convert all inputs to bf16 (single launch)
    conv_all<<<dim3(CONV_BLOCKS), 256>>>((const float4*)feat, (const float4*)wq,
                                         (const float4*)wk, (const float4*)wv);

    // QKV: 4 col blocks (512/128), 128 row blocks (16384/128), z = {q,k,v}
    qkv_bf16<<<dim3(4, 128, 3), 256, SMEM_NT_BYTES>>>(bq, bk, bv);

    // Per-batch pipeline: scores_b on the main stream; pv_b on s1 as soon as
    // scores_b is done. pv_b (64 CTAs) co-schedules with scores_{b+1} (256
    // CTAs), filling pv's wave-quantization tail.
    for (int b = 0; b < BATCH; b++) {
        scores_bf16<<<dim3(16, 16, 1), 256, SMEM_NT_BYTES>>>(b);
        cudaEventRecord(evb[b], 0);
        cudaStreamWaitEvent(s1, evb[b], 0);
        pv_bf16<<<dim3(4, 16, 1), 256, SMEM_PV_BYTES, s1>>>(feat, out, b);
    }
    // Join: main stream (the captured one) waits for all pv work.
    cudaEventRecord(evj, s1);
    cudaStreamWaitEvent(0, evj, 0);
}

// round 13
// speedup vs baseline: 1.0326x; 1.0326x over previous
#include <cuda_runtime.h>
#include <cuda_bf16.h>
#include <cstdint>

#define BATCH 8
#define NSEQ  2048
#define CDIM  512

// ---------------------------------------------------------------------------
// Scratch (__device__ globals per allocation-free rule)
// ---------------------------------------------------------------------------
__device__ __align__(16) __nv_bfloat16 g_fb[BATCH * NSEQ * CDIM];      // feat bf16
__device__ __align__(16) __nv_bfloat16 g_wb[3 * CDIM * CDIM];          // wq,wk,wv bf16
__device__ __align__(16) __nv_bfloat16 g_qb[BATCH * NSEQ * CDIM];
__device__ __align__(16) __nv_bfloat16 g_kb[BATCH * NSEQ * CDIM];
__device__ __align__(16) __nv_bfloat16 g_vt[BATCH * CDIM * NSEQ];      // V transposed [b][d][m]
__device__ __align__(16) __nv_bfloat16 g_s[(size_t)BATCH * NSEQ * NSEQ];  // exp(S-30)
// 32 partial sums per row: 16 col-blocks x 2 n-warps.
__device__ __align__(16) float g_spart[BATCH * NSEQ * 32];

// ---------------------------------------------------------------------------
// Helpers
// ---------------------------------------------------------------------------
__device__ __forceinline__ uint32_t smem_to_u32(const void* p) {
    uint32_t a;
    asm("{ .reg .u64 t; cvta.to.shared.u64 t, %1; cvt.u32.u64 %0, t; }" : "=r"(a) : "l"(p));
    return a;
}

__device__ __forceinline__ void cp_async16(uint32_t saddr, const void* gptr) {
    asm volatile("cp.async.cg.shared.global [%0], [%1], 16;" :: "r"(saddr), "l"(gptr));
}
#define CP_COMMIT() asm volatile("cp.async.commit_group;" ::: "memory")
#define CP_WAIT0()  asm volatile("cp.async.wait_group 0;" ::: "memory")

__device__ __forceinline__ void ldsm4(uint32_t r[4], uint32_t addr) {
    asm volatile("ldmatrix.sync.aligned.m8n8.x4.shared.b16 {%0,%1,%2,%3}, [%4];"
        : "=r"(r[0]), "=r"(r[1]), "=r"(r[2]), "=r"(r[3]) : "r"(addr));
}

__device__ __forceinline__ void mma_bf16(float c[4], const uint32_t a[4], const uint32_t b[2]) {
    asm volatile(
        "mma.sync.aligned.m16n8k16.row.col.f32.bf16.bf16.f32 "
        "{%0,%1,%2,%3}, {%4,%5,%6,%7}, {%8,%9}, {%0,%1,%2,%3};"
        : "+f"(c[0]), "+f"(c[1]), "+f"(c[2]), "+f"(c[3])
        : "r"(a[0]), "r"(a[1]), "r"(a[2]), "r"(a[3]), "r"(b[0]), "r"(b[1]));
}

__device__ __forceinline__ uint32_t packbf(float x, float y) {
    __nv_bfloat162 h = __floats2bfloat162_rn(x, y);
    return *reinterpret_cast<uint32_t*>(&h);
}

// ---------------------------------------------------------------------------
// SMEM tile layout (bf16, padded rows so ldmatrix 16B units hit distinct banks)
//   NT tile: 128 rows x 64 k-bf16, row stride 72 bf16 = 144 B -> 18432 B
// All three GEMMs now use NT tiles for both operands.
// ---------------------------------------------------------------------------
#define NT_TILE_B 18432

__device__ __forceinline__ void load_ntb(const __nv_bfloat16* __restrict__ g, long ld,
                                         int rowBase, int kt, uint32_t sbase, int tid) {
    #pragma unroll
    for (int i = 0; i < 4; i++) {
        int idx = i * 256 + tid;      // 1024 chunks of 16B
        int r = idx >> 3, f8 = idx & 7;
        cp_async16(sbase + (uint32_t)(r * 144 + f8 * 16),
                   g + (long)(rowBase + r) * ld + kt + f8 * 8);
    }
}

// One 64-k slab, warp tile 32x64, both operands NT (plain ldsm4).
__device__ __forceinline__ void slab_bf16(uint32_t aBase, uint32_t bBase,
                                          float acc[2][8][4], int m0, int n0, int lane) {
    uint32_t aOff[2], bOff[4];
    #pragma unroll
    for (int mt = 0; mt < 2; mt++)
        aOff[mt] = (uint32_t)((m0 + mt * 16 + (lane & 15)) * 144 + ((lane & 16) ? 16 : 0));
    #pragma unroll
    for (int nt2 = 0; nt2 < 4; nt2++)
        bOff[nt2] = (uint32_t)((n0 + nt2 * 16 + (lane & 7) + ((lane & 16) ? 8 : 0)) * 144
                    + ((lane & 8) ? 16 : 0));
    #pragma unroll
    for (int kk = 0; kk < 4; kk++) {
        uint32_t a[2][4];
        ldsm4(a[0], aBase + aOff[0] + kk * 32);
        ldsm4(a[1], aBase + aOff[1] + kk * 32);
        uint32_t b[4][4];
        #pragma unroll
        for (int nt2 = 0; nt2 < 4; nt2++)
            ldsm4(b[nt2], bBase + bOff[nt2] + kk * 32);
        #pragma unroll
        for (int mt = 0; mt < 2; mt++)
            #pragma unroll
            for (int nt2 = 0; nt2 < 4; nt2++) {
                mma_bf16(acc[mt][nt2 * 2 + 0], a[mt], &b[nt2][0]);
                mma_bf16(acc[mt][nt2 * 2 + 1], a[mt], &b[nt2][2]);
            }
    }
}

// ---------------------------------------------------------------------------
// Combined convert kernel (f32 -> bf16): feat (2,097,152 float4s) then the
// three weight matrices (3 x 65,536 float4s). One launch.
// ---------------------------------------------------------------------------
#define FEAT_F4 (BATCH * NSEQ * CDIM / 4)          // 2097152
#define W_F4    (CDIM * CDIM / 4)                  // 65536
#define CONV_BLOCKS ((FEAT_F4 + 3 * W_F4) / 256)   // 8960

__global__ __launch_bounds__(256) void conv_all(const float4* __restrict__ feat,
                                                const float4* __restrict__ wq,
                                                const float4* __restrict__ wk,
                                                const float4* __restrict__ wv) {
    int idx = blockIdx.x * 256 + threadIdx.x;
    const float4* src;
    uint2* dst;
    int off;
    if (idx < FEAT_F4) {
        src = feat;             dst = (uint2*)g_fb; off = idx;
    } else if (idx < FEAT_F4 + W_F4) {
        src = wq;  dst = (uint2*)g_wb;              off = idx - FEAT_F4;
    } else if (idx < FEAT_F4 + 2 * W_F4) {
        src = wk;  dst = (uint2*)g_wb + W_F4;       off = idx - FEAT_F4 - W_F4;
    } else {
        src = wv;  dst = (uint2*)g_wb + 2 * W_F4;   off = idx - FEAT_F4 - 2 * W_F4;
    }
    float4 v = src[off];
    uint2 o;
    o.x = packbf(v.x, v.y);
    o.y = packbf(v.z, v.w);
    dst[off] = o;
}

// ---------------------------------------------------------------------------
// Kernel 1: QKV projections (NT). CTA 128x128, 256 thr, 2-stage pipeline.
// z in {0,1}: write row-major to g_qb/g_kb. z==2: write V TRANSPOSED to
// g_vt[b][d][m] via an SMEM-staged, fully-coalesced store.
// ---------------------------------------------------------------------------
__global__ __launch_bounds__(256, 2) void qkv_bf16(
    const float* __restrict__ bq, const float* __restrict__ bk,
    const float* __restrict__ bv)
{
    extern __shared__ char sm[];
    uint32_t sb = smem_to_u32(sm);
    const int tid = threadIdx.x;
    const int wid = tid >> 5, lane = tid & 31;
    const int lq = lane >> 2, lr = lane & 3;
    const int m0 = (wid >> 1) * 32, n0 = (wid & 1) * 64;
    const int z = blockIdx.z;
    const __nv_bfloat16* W = g_wb + (long)z * CDIM * CDIM;
    const float* bias = (z == 0) ? bq : (z == 1) ? bk : bv;

    const int rowBase = blockIdx.y * 128;
    const int colBase = blockIdx.x * 128;

    uint32_t aAddr[2] = { sb, sb + NT_TILE_B };
    uint32_t bAddr[2] = { sb + 2 * NT_TILE_B, sb + 3 * NT_TILE_B };

    float acc[2][8][4] = {};

    load_ntb(g_fb, CDIM, rowBase, 0, aAddr[0], tid);
    load_ntb(W,    CDIM, colBase, 0, bAddr[0], tid);
    CP_COMMIT(); CP_WAIT0();
    __syncthreads();

    const int nslab = CDIM / 64;
    for (int s = 0; s < nslab; s++) {
        int cur = s & 1;
        if (s + 1 < nslab) {
            int nxt = cur ^ 1;
            load_ntb(g_fb, CDIM, rowBase, (s + 1) * 64, aAddr[nxt], tid);
            load_ntb(W,    CDIM, colBase, (s + 1) * 64, bAddr[nxt], tid);
            CP_COMMIT();
        }
        slab_bf16(aAddr[cur], bAddr[cur], acc, m0, n0, lane);
        if (s + 1 < nslab) CP_WAIT0();
        __syncthreads();
    }

    if (z < 2) {
        __nv_bfloat16* out = (z == 0) ? g_qb : g_kb;
        #pragma unroll
        for (int mt = 0; mt < 2; mt++)
            #pragma unroll
            for (int half = 0; half < 2; half++) {
                int row = rowBase + m0 + mt * 16 + lq + half * 8;
                #pragma unroll
                for (int nt = 0; nt < 8; nt++) {
                    int col = colBase + n0 + nt * 8 + lr * 2;
                    uint32_t p = packbf(acc[mt][nt][half * 2 + 0] + bias[col + 0],
                                        acc[mt][nt][half * 2 + 1] + bias[col + 1]);
                    *(uint32_t*)&out[(long)row * CDIM + col] = p;
                }
            }
    } else {
        // Stage the 128x128 tile transposed in SMEM ([col][row], stride 136),
        // then write coalesced 16B chunks along m into g_vt[b][d][m].
        __nv_bfloat16* T = (__nv_bfloat16*)sm;   // 128 * 136 bf16 = 34816 B
        #pragma unroll
        for (int mt = 0; mt < 2; mt++)
            #pragma unroll
            for (int half = 0; half < 2; half++) {
                int rowl = m0 + mt * 16 + lq + half * 8;
                #pragma unroll
                for (int nt = 0; nt < 8; nt++) {
                    int coll = n0 + nt * 8 + lr * 2;
                    T[(coll + 0) * 136 + rowl] =
                        __float2bfloat16(acc[mt][nt][half * 2 + 0] + bias[colBase + coll + 0]);
                    T[(coll + 1) * 136 + rowl] =
                        __float2bfloat16(acc[mt][nt][half * 2 + 1] + bias[colBase + coll + 1]);
                }
            }
        __syncthreads();
        const int bb = rowBase >> 11;            // batch
        const int mg = rowBase & (NSEQ - 1);     // m offset within batch
        __nv_bfloat16* vt = g_vt + (long)bb * CDIM * NSEQ;
        #pragma unroll
        for (int i = 0; i < 8; i++) {
            int idx = i * 256 + tid;             // 2048 chunks of 16B
            int col = idx >> 4, ch = idx & 15;
            uint4 v = *(const uint4*)&T[col * 136 + ch * 8];
            *(uint4*)&vt[(long)(colBase + col) * NSEQ + mg + ch * 8] = v;
        }
    }
}

// ---------------------------------------------------------------------------
// Kernel 2: scores (NT). CTA 128x128. Writes exp(S - 30) in bf16, plus one
// partial row-sum per (row, 64-col warp span): slot = blockIdx.x*2 + n0/64.
// ---------------------------------------------------------------------------
__global__ __launch_bounds__(256, 2) void scores_bf16()
{
    extern __shared__ char sm[];
    uint32_t sb = smem_to_u32(sm);
    const int tid = threadIdx.x;
    const int wid = tid >> 5, lane = tid & 31;
    const int lq = lane >> 2, lr = lane & 3;
    const int m0 = (wid >> 1) * 32, n0 = (wid & 1) * 64;
    const int bz = blockIdx.z;

    const __nv_bfloat16* Aq = g_qb + (long)bz * NSEQ * CDIM;
    const __nv_bfloat16* Bk = g_kb + (long)bz * NSEQ * CDIM;
    __nv_bfloat16* out = g_s + (size_t)bz * NSEQ * NSEQ;
    const int rowBase = blockIdx.y * 128;
    const int colBase = blockIdx.x * 128;

    uint32_t aAddr[2] = { sb, sb + NT_TILE_B };
    uint32_t bAddr[2] = { sb + 2 * NT_TILE_B, sb + 3 * NT_TILE_B };

    float acc[2][8][4] = {};

    load_ntb(Aq, CDIM, rowBase, 0, aAddr[0], tid);
    load_ntb(Bk, CDIM, colBase, 0, bAddr[0], tid);
    CP_COMMIT(); CP_WAIT0();
    __syncthreads();

    const int nslab = CDIM / 64;
    for (int s = 0; s < nslab; s++) {
        int cur = s & 1;
        if (s + 1 < nslab) {
            int nxt = cur ^ 1;
            load_ntb(Aq, CDIM, rowBase, (s + 1) * 64, aAddr[nxt], tid);
            load_ntb(Bk, CDIM, colBase, (s + 1) * 64, bAddr[nxt], tid);
            CP_COMMIT();
        }
        slab_bf16(aAddr[cur], bAddr[cur], acc, m0, n0, lane);
        if (s + 1 < nslab) CP_WAIT0();
        __syncthreads();
    }

    // Epilogue: exp(s - 30) (unnormalized softmax numerator; constant offset
    // cancels in pv's normalize) + per-row partial sums via lr-quad reduce.
    #pragma unroll
    for (int mt = 0; mt < 2; mt++)
        #pragma unroll
        for (int half = 0; half < 2; half++) {
            int row = rowBase + m0 + mt * 16 + lq + half * 8;
            float rp = 0.f;
            #pragma unroll
            for (int nt = 0; nt < 8; nt++) {
                int col = colBase + n0 + nt * 8 + lr * 2;
                float e0 = __expf(acc[mt][nt][half * 2 + 0] - 30.0f);
                float e1 = __expf(acc[mt][nt][half * 2 + 1] - 30.0f);
                rp += e0 + e1;
                *(uint32_t*)&out[(size_t)row * NSEQ + col] = packbf(e0, e1);
            }
            // Lanes lq*4 + {0..3} hold the same row; combine their spans.
            rp += __shfl_xor_sync(0xffffffffu, rp, 1);
            rp += __shfl_xor_sync(0xffffffffu, rp, 2);
            if (lr == 0) {
                int part = blockIdx.x * 2 + (n0 >> 6);   // 0..31, unique per warp
                g_spart[((size_t)(bz * NSEQ) + row) * 32 + part] = rp;
            }
        }
}

// ---------------------------------------------------------------------------
// Kernel 3: PV + residual + normalize. CTA 128x128, 2-stage. A = exp(S),
// B = g_vt (d rows, m contiguous) -> plain NT path, identical to scores.
// out = feat + acc * (1/sqrt(C)) / rowsum (rowsum from g_spart partials).
// ---------------------------------------------------------------------------
__global__ __launch_bounds__(256, 2) void pv_bf16(const float* __restrict__ feat,
                                                  float* __restrict__ out)
{
    extern __shared__ char sm[];
    uint32_t sb = smem_to_u32(sm);
    const int tid = threadIdx.x;
    const int wid = tid >> 5, lane = tid & 31;
    const int lq = lane >> 2, lr = lane & 3;
    const int m0 = (wid >> 1) * 32, n0 = (wid & 1) * 64;
    const int bz = blockIdx.z;

    const __nv_bfloat16* Ap = g_s + (size_t)bz * NSEQ * NSEQ;
    const __nv_bfloat16* Bv = g_vt + (long)bz * CDIM * NSEQ;
    const int rowBase = blockIdx.y * 128;
    const int colBase = blockIdx.x * 128;

    uint32_t aAddr[2] = { sb, sb + NT_TILE_B };
    uint32_t bAddr[2] = { sb + 2 * NT_TILE_B, sb + 3 * NT_TILE_B };

    float acc[2][8][4] = {};

    load_ntb(Ap, NSEQ, rowBase, 0, aAddr[0], tid);
    load_ntb(Bv, NSEQ, colBase, 0, bAddr[0], tid);
    CP_COMMIT(); CP_WAIT0();
    __syncthreads();

    const int nslab = NSEQ / 64;
    for (int s = 0; s < nslab; s++) {
        int cur = s & 1;
        if (s + 1 < nslab) {
            int nxt = cur ^ 1;
            load_ntb(Ap, NSEQ, rowBase, (s + 1) * 64, aAddr[nxt], tid);
            load_ntb(Bv, NSEQ, colBase, (s + 1) * 64, bAddr[nxt], tid);
            CP_COMMIT();
        }
        slab_bf16(aAddr[cur], bAddr[cur], acc, m0, n0, lane);
        if (s + 1 < nslab) CP_WAIT0();
        __syncthreads();
    }

    // Gather row normalizers: 32 partials per row -> smem (reuses tile smem;
    // the mainloop's final __syncthreads has retired all tile reads).
    float* rsh = (float*)sm;
    if (tid < 128) {
        const float4* p = (const float4*)(g_spart + ((size_t)(bz * NSEQ) + rowBase + tid) * 32);
        float ssum = 0.f;
        #pragma unroll
        for (int i = 0; i < 8; i++) {
            float4 v = p[i];
            ssum += (v.x + v.y) + (v.z + v.w);
        }
        rsh[tid] = 0.044194173824159216f / ssum;   // (1/sqrt(512)) / rowsum
    }
    __syncthreads();

    #pragma unroll
    for (int mt = 0; mt < 2; mt++)
        #pragma unroll
        for (int half = 0; half < 2; half++) {
            int rloc = m0 + mt * 16 + lq + half * 8;
            long gRow = (long)bz * NSEQ + rowBase + rloc;
            const float nrm = rsh[rloc];
            #pragma unroll
            for (int nt = 0; nt < 8; nt++) {
                int col = colBase + n0 + nt * 8 + lr * 2;
                float2 f = *(const float2*)&feat[gRow * CDIM + col];
                float2 o;
                o.x = fmaf(acc[mt][nt][half * 2 + 0], nrm, f.x);
                o.y = fmaf(acc[mt][nt][half * 2 + 1], nrm, f.y);
                *(float2*)&out[gRow * CDIM + col] = o;
            }
        }
}

// ---------------------------------------------------------------------------
#define SMEM_NT_BYTES (4 * NT_TILE_B)                 // 73728 (all GEMM kernels)

extern "C" void kernel_launch(void* const* d_in, const int* in_sizes, int n_in,
                              void* d_out, int out_size)
{
    const float* feat = (const float*)d_in[0];
    const float* wq   = (const float*)d_in[1];
    const float* bq   = (const float*)d_in[2];
    const float* wk   = (const float*)d_in[3];
    const float* bk   = (const float*)d_in[4];
    const float* wv   = (const float*)d_in[5];
    const float* bv   = (const float*)d_in[6];
    float* out = (float*)d_out;

    cudaFuncSetAttribute(qkv_bf16,    cudaFuncAttributeMaxDynamicSharedMemorySize, SMEM_NT_BYTES);
    cudaFuncSetAttribute(scores_bf16, cudaFuncAttributeMaxDynamicSharedMemorySize, SMEM_NT_BYTES);
    cudaFuncSetAttribute(pv_bf16,     cudaFuncAttributeMaxDynamicSharedMemorySize, SMEM_NT_BYTES);

    // Convert all inputs to bf16 (single launch)
    conv_all<<<dim3(CONV_BLOCKS), 256>>>((const float4*)feat, (const float4*)wq,
                                         (const float4*)wk, (const float4*)wv);

    // QKV: 4 col blocks (512/128), 128 row blocks (16384/128), z = {q,k,v}
    qkv_bf16<<<dim3(4, 128, 3), 256, SMEM_NT_BYTES>>>(bq, bk, bv);
    // Scores + exp + row partial sums: 16x16 blocks, 8 batches
    scores_bf16<<<dim3(16, 16, 8), 256, SMEM_NT_BYTES>>>();
    // PV + residual + normalize: 4 col blocks (d), 16 row blocks, 8 batches
    pv_bf16<<<dim3(4, 16, 8), 256, SMEM_NT_BYTES>>>(feat, out);
}

// round 14
// speedup vs baseline: 1.4851x; 1.4382x over previous
#include <cuda_runtime.h>
#include <cuda_bf16.h>
#include <cstdint>

#define BATCH 8
#define NSEQ  2048
#define CDIM  512

// ---------------------------------------------------------------------------
// Scratch (__device__ globals per allocation-free rule)
// ---------------------------------------------------------------------------
__device__ __align__(16) __nv_bfloat16 g_fb[BATCH * NSEQ * CDIM];      // feat bf16
__device__ __align__(16) __nv_bfloat16 g_wb[3 * CDIM * CDIM];          // wq,wk,wv bf16
__device__ __align__(16) __nv_bfloat16 g_qb[BATCH * NSEQ * CDIM];
__device__ __align__(16) __nv_bfloat16 g_kb[BATCH * NSEQ * CDIM];
__device__ __align__(16) __nv_bfloat16 g_vb[BATCH * NSEQ * CDIM];      // natural [m][d]
__device__ __align__(16) __nv_bfloat16 g_s[(size_t)BATCH * NSEQ * NSEQ];  // exp(S-30)
// 32 partial sums per row: 16 col-blocks x 2 n-warps.
__device__ __align__(16) float g_spart[BATCH * NSEQ * 32];

// ---------------------------------------------------------------------------
// Helpers
// ---------------------------------------------------------------------------
__device__ __forceinline__ uint32_t smem_to_u32(const void* p) {
    uint32_t a;
    asm("{ .reg .u64 t; cvta.to.shared.u64 t, %1; cvt.u32.u64 %0, t; }" : "=r"(a) : "l"(p));
    return a;
}

__device__ __forceinline__ void cp_async16(uint32_t saddr, const void* gptr) {
    asm volatile("cp.async.cg.shared.global [%0], [%1], 16;" :: "r"(saddr), "l"(gptr));
}
#define CP_COMMIT() asm volatile("cp.async.commit_group;" ::: "memory")
#define CP_WAIT0()  asm volatile("cp.async.wait_group 0;" ::: "memory")

__device__ __forceinline__ void ldsm4(uint32_t r[4], uint32_t addr) {
    asm volatile("ldmatrix.sync.aligned.m8n8.x4.shared.b16 {%0,%1,%2,%3}, [%4];"
        : "=r"(r[0]), "=r"(r[1]), "=r"(r[2]), "=r"(r[3]) : "r"(addr));
}
__device__ __forceinline__ void ldsm4t(uint32_t r[4], uint32_t addr) {
    asm volatile("ldmatrix.sync.aligned.m8n8.x4.trans.shared.b16 {%0,%1,%2,%3}, [%4];"
        : "=r"(r[0]), "=r"(r[1]), "=r"(r[2]), "=r"(r[3]) : "r"(addr));
}

__device__ __forceinline__ void mma_bf16(float c[4], const uint32_t a[4], const uint32_t b[2]) {
    asm volatile(
        "mma.sync.aligned.m16n8k16.row.col.f32.bf16.bf16.f32 "
        "{%0,%1,%2,%3}, {%4,%5,%6,%7}, {%8,%9}, {%0,%1,%2,%3};"
        : "+f"(c[0]), "+f"(c[1]), "+f"(c[2]), "+f"(c[3])
        : "r"(a[0]), "r"(a[1]), "r"(a[2]), "r"(a[3]), "r"(b[0]), "r"(b[1]));
}

__device__ __forceinline__ uint32_t packbf(float x, float y) {
    __nv_bfloat162 h = __floats2bfloat162_rn(x, y);
    return *reinterpret_cast<uint32_t*>(&h);
}

// ---------------------------------------------------------------------------
// SMEM tile layouts (bf16, padded rows so ldmatrix 16B units hit distinct banks)
//   NT tile: 128 rows x 64 k-bf16, row stride 72 bf16 = 144 B -> 18432 B
//   NN tile:  64 k-rows x 128 n-bf16, row stride 136 bf16 = 272 B -> 17408 B
// ---------------------------------------------------------------------------
#define NT_TILE_B 18432
#define NN_TILE_B 17408

__device__ __forceinline__ void load_ntb(const __nv_bfloat16* __restrict__ g, long ld,
                                         int rowBase, int kt, uint32_t sbase, int tid) {
    #pragma unroll
    for (int i = 0; i < 4; i++) {
        int idx = i * 256 + tid;      // 1024 chunks of 16B
        int r = idx >> 3, f8 = idx & 7;
        cp_async16(sbase + (uint32_t)(r * 144 + f8 * 16),
                   g + (long)(rowBase + r) * ld + kt + f8 * 8);
    }
}

__device__ __forceinline__ void load_nnb(const __nv_bfloat16* __restrict__ g, long ld,
                                         int colBase, int kt, uint32_t sbase, int tid) {
    #pragma unroll
    for (int i = 0; i < 4; i++) {
        int idx = i * 256 + tid;
        int r = idx >> 4, c8 = idx & 15;
        cp_async16(sbase + (uint32_t)(r * 272 + c8 * 16),
                   g + (long)(kt + r) * ld + colBase + c8 * 8);
    }
}

// One 64-k slab, warp tile 32x64. A from NT tile; B NT (BNN=0) or NN+trans (BNN=1).
template<int BNN>
__device__ __forceinline__ void slab_bf16(uint32_t aBase, uint32_t bBase,
                                          float acc[2][8][4], int m0, int n0, int lane) {
    uint32_t aOff[2], bOff[4];
    #pragma unroll
    for (int mt = 0; mt < 2; mt++)
        aOff[mt] = (uint32_t)((m0 + mt * 16 + (lane & 15)) * 144 + ((lane & 16) ? 16 : 0));
    #pragma unroll
    for (int nt2 = 0; nt2 < 4; nt2++) {
        if (BNN)
            bOff[nt2] = (uint32_t)(((lane & 7) + ((lane & 8) ? 8 : 0)) * 272
                        + (n0 + nt2 * 16) * 2 + ((lane & 16) ? 16 : 0));
        else
            bOff[nt2] = (uint32_t)((n0 + nt2 * 16 + (lane & 7) + ((lane & 16) ? 8 : 0)) * 144
                        + ((lane & 8) ? 16 : 0));
    }
    #pragma unroll
    for (int kk = 0; kk < 4; kk++) {
        uint32_t a[2][4];
        ldsm4(a[0], aBase + aOff[0] + kk * 32);
        ldsm4(a[1], aBase + aOff[1] + kk * 32);
        uint32_t b[4][4];
        #pragma unroll
        for (int nt2 = 0; nt2 < 4; nt2++) {
            if (BNN) ldsm4t(b[nt2], bBase + bOff[nt2] + kk * 16 * 272);
            else     ldsm4 (b[nt2], bBase + bOff[nt2] + kk * 32);
        }
        #pragma unroll
        for (int mt = 0; mt < 2; mt++)
            #pragma unroll
            for (int nt2 = 0; nt2 < 4; nt2++) {
                mma_bf16(acc[mt][nt2 * 2 + 0], a[mt], &b[nt2][0]);
                mma_bf16(acc[mt][nt2 * 2 + 1], a[mt], &b[nt2][2]);
            }
    }
}

// ---------------------------------------------------------------------------
// Combined convert kernel (f32 -> bf16): feat (2,097,152 float4s) then the
// three weight matrices (3 x 65,536 float4s). One launch. Feat is read with
// streaming hint (read-once; keep L2 for reused data).
// ---------------------------------------------------------------------------
#define FEAT_F4 (BATCH * NSEQ * CDIM / 4)          // 2097152
#define W_F4    (CDIM * CDIM / 4)                  // 65536
#define CONV_BLOCKS ((FEAT_F4 + 3 * W_F4) / 256)   // 8960

__global__ __launch_bounds__(256) void conv_all(const float4* __restrict__ feat,
                                                const float4* __restrict__ wq,
                                                const float4* __restrict__ wk,
                                                const float4* __restrict__ wv) {
    int idx = blockIdx.x * 256 + threadIdx.x;
    float4 v;
    uint2* dst;
    int off;
    if (idx < FEAT_F4) {
        off = idx;                  v = __ldcs(&feat[off]); dst = (uint2*)g_fb;
    } else if (idx < FEAT_F4 + W_F4) {
        off = idx - FEAT_F4;        v = wq[off];            dst = (uint2*)g_wb;
    } else if (idx < FEAT_F4 + 2 * W_F4) {
        off = idx - FEAT_F4 - W_F4; v = wk[off];            dst = (uint2*)g_wb + W_F4;
    } else {
        off = idx - FEAT_F4 - 2 * W_F4; v = wv[off];        dst = (uint2*)g_wb + 2 * W_F4;
    }
    uint2 o;
    o.x = packbf(v.x, v.y);
    o.y = packbf(v.z, v.w);
    dst[off] = o;
}

// ---------------------------------------------------------------------------
// Kernel 1: QKV projections (NT). CTA 128x128, 256 thr, 2-stage pipeline.
// M=16384, N=512, K=512
// ---------------------------------------------------------------------------
__global__ __launch_bounds__(256, 2) void qkv_bf16(
    const float* __restrict__ bq, const float* __restrict__ bk,
    const float* __restrict__ bv)
{
    extern __shared__ char sm[];
    uint32_t sb = smem_to_u32(sm);
    const int tid = threadIdx.x;
    const int wid = tid >> 5, lane = tid & 31;
    const int lq = lane >> 2, lr = lane & 3;
    const int m0 = (wid >> 1) * 32, n0 = (wid & 1) * 64;
    const int z = blockIdx.z;
    const __nv_bfloat16* W = g_wb + (long)z * CDIM * CDIM;
    const float* bias = (z == 0) ? bq : (z == 1) ? bk : bv;
    __nv_bfloat16* out = (z == 0) ? g_qb : (z == 1) ? g_kb : g_vb;

    const int rowBase = blockIdx.y * 128;
    const int colBase = blockIdx.x * 128;

    uint32_t aAddr[2] = { sb, sb + NT_TILE_B };
    uint32_t bAddr[2] = { sb + 2 * NT_TILE_B, sb + 3 * NT_TILE_B };

    float acc[2][8][4] = {};

    load_ntb(g_fb, CDIM, rowBase, 0, aAddr[0], tid);
    load_ntb(W,    CDIM, colBase, 0, bAddr[0], tid);
    CP_COMMIT(); CP_WAIT0();
    __syncthreads();

    const int nslab = CDIM / 64;
    for (int s = 0; s < nslab; s++) {
        int cur = s & 1;
        if (s + 1 < nslab) {
            int nxt = cur ^ 1;
            load_ntb(g_fb, CDIM, rowBase, (s + 1) * 64, aAddr[nxt], tid);
            load_ntb(W,    CDIM, colBase, (s + 1) * 64, bAddr[nxt], tid);
            CP_COMMIT();
        }
        slab_bf16<0>(aAddr[cur], bAddr[cur], acc, m0, n0, lane);
        if (s + 1 < nslab) CP_WAIT0();
        __syncthreads();
    }

    #pragma unroll
    for (int mt = 0; mt < 2; mt++)
        #pragma unroll
        for (int half = 0; half < 2; half++) {
            int row = rowBase + m0 + mt * 16 + lq + half * 8;
            #pragma unroll
            for (int nt = 0; nt < 8; nt++) {
                int col = colBase + n0 + nt * 8 + lr * 2;
                uint32_t p = packbf(acc[mt][nt][half * 2 + 0] + bias[col + 0],
                                    acc[mt][nt][half * 2 + 1] + bias[col + 1]);
                *(uint32_t*)&out[(long)row * CDIM + col] = p;
            }
        }
}

// ---------------------------------------------------------------------------
// Kernel 2: scores (NT). CTA 128x128. Writes exp(S - 30) in bf16, plus one
// partial row-sum per (row, 64-col warp span): slot = blockIdx.x*2 + n0/64.
// ---------------------------------------------------------------------------
__global__ __launch_bounds__(256, 2) void scores_bf16()
{
    extern __shared__ char sm[];
    uint32_t sb = smem_to_u32(sm);
    const int tid = threadIdx.x;
    const int wid = tid >> 5, lane = tid & 31;
    const int lq = lane >> 2, lr = lane & 3;
    const int m0 = (wid >> 1) * 32, n0 = (wid & 1) * 64;
    const int bz = blockIdx.z;

    const __nv_bfloat16* Aq = g_qb + (long)bz * NSEQ * CDIM;
    const __nv_bfloat16* Bk = g_kb + (long)bz * NSEQ * CDIM;
    __nv_bfloat16* out = g_s + (size_t)bz * NSEQ * NSEQ;
    const int rowBase = blockIdx.y * 128;
    const int colBase = blockIdx.x * 128;

    uint32_t aAddr[2] = { sb, sb + NT_TILE_B };
    uint32_t bAddr[2] = { sb + 2 * NT_TILE_B, sb + 3 * NT_TILE_B };

    float acc[2][8][4] = {};

    load_ntb(Aq, CDIM, rowBase, 0, aAddr[0], tid);
    load_ntb(Bk, CDIM, colBase, 0, bAddr[0], tid);
    CP_COMMIT(); CP_WAIT0();
    __syncthreads();

    const int nslab = CDIM / 64;
    for (int s = 0; s < nslab; s++) {
        int cur = s & 1;
        if (s + 1 < nslab) {
            int nxt = cur ^ 1;
            load_ntb(Aq, CDIM, rowBase, (s + 1) * 64, aAddr[nxt], tid);
            load_ntb(Bk, CDIM, colBase, (s + 1) * 64, bAddr[nxt], tid);
            CP_COMMIT();
        }
        slab_bf16<0>(aAddr[cur], bAddr[cur], acc, m0, n0, lane);
        if (s + 1 < nslab) CP_WAIT0();
        __syncthreads();
    }

    // Epilogue: exp(s - 30) (unnormalized softmax numerator; constant offset
    // cancels in pv's normalize) + per-row partial sums via lr-quad reduce.
    #pragma unroll
    for (int mt = 0; mt < 2; mt++)
        #pragma unroll
        for (int half = 0; half < 2; half++) {
            int row = rowBase + m0 + mt * 16 + lq + half * 8;
            float rp = 0.f;
            #pragma unroll
            for (int nt = 0; nt < 8; nt++) {
                int col = colBase + n0 + nt * 8 + lr * 2;
                float e0 = __expf(acc[mt][nt][half * 2 + 0] - 30.0f);
                float e1 = __expf(acc[mt][nt][half * 2 + 1] - 30.0f);
                rp += e0 + e1;
                *(uint32_t*)&out[(size_t)row * NSEQ + col] = packbf(e0, e1);
            }
            // Lanes lq*4 + {0..3} hold the same row; combine their spans.
            rp += __shfl_xor_sync(0xffffffffu, rp, 1);
            rp += __shfl_xor_sync(0xffffffffu, rp, 2);
            if (lr == 0) {
                int part = blockIdx.x * 2 + (n0 >> 6);   // 0..31, unique per warp
                g_spart[((size_t)(bz * NSEQ) + row) * 32 + part] = rp;
            }
        }
}

// ---------------------------------------------------------------------------
// Kernel 3: PV + residual + normalize. CTA 128x128, 2-stage. A = exp(S),
// B = V [m][d] via trans ldmatrix. Epilogue uses streaming loads/stores for
// feat/out (read/write-once f32, 128 MB) so exp(S) stays L2-resident.
// out = feat + acc * (1/sqrt(C)) / rowsum (rowsum from g_spart partials).
// ---------------------------------------------------------------------------
__global__ __launch_bounds__(256, 2) void pv_bf16(const float* __restrict__ feat,
                                                  float* __restrict__ out)
{
    extern __shared__ char sm[];
    uint32_t sb = smem_to_u32(sm);
    const int tid = threadIdx.x;
    const int wid = tid >> 5, lane = tid & 31;
    const int lq = lane >> 2, lr = lane & 3;
    const int m0 = (wid >> 1) * 32, n0 = (wid & 1) * 64;
    const int bz = blockIdx.z;

    const __nv_bfloat16* Ap = g_s + (size_t)bz * NSEQ * NSEQ;
    const __nv_bfloat16* Bv = g_vb + (long)bz * NSEQ * CDIM;
    const int rowBase = blockIdx.y * 128;
    const int colBase = blockIdx.x * 128;

    uint32_t aAddr[2] = { sb, sb + NT_TILE_B };
    uint32_t bAddr[2] = { sb + 2 * NT_TILE_B, sb + 2 * NT_TILE_B + NN_TILE_B };

    float acc[2][8][4] = {};

    load_ntb(Ap, NSEQ, rowBase, 0, aAddr[0], tid);
    load_nnb(Bv, CDIM, colBase, 0, bAddr[0], tid);
    CP_COMMIT(); CP_WAIT0();
    __syncthreads();

    const int nslab = NSEQ / 64;
    for (int s = 0; s < nslab; s++) {
        int cur = s & 1;
        if (s + 1 < nslab) {
            int nxt = cur ^ 1;
            load_ntb(Ap, NSEQ, rowBase, (s + 1) * 64, aAddr[nxt], tid);
            load_nnb(Bv, CDIM, colBase, (s + 1) * 64, bAddr[nxt], tid);
            CP_COMMIT();
        }
        slab_bf16<1>(aAddr[cur], bAddr[cur], acc, m0, n0, lane);
        if (s + 1 < nslab) CP_WAIT0();
        __syncthreads();
    }

    // Gather row normalizers: 32 partials per row -> smem (reuses tile smem;
    // the mainloop's final __syncthreads has retired all tile reads).
    float* rsh = (float*)sm;
    if (tid < 128) {
        const float4* p = (const float4*)(g_spart + ((size_t)(bz * NSEQ) + rowBase + tid) * 32);
        float ssum = 0.f;
        #pragma unroll
        for (int i = 0; i < 8; i++) {
            float4 v = p[i];
            ssum += (v.x + v.y) + (v.z + v.w);
        }
        rsh[tid] = 0.044194173824159216f / ssum;   // (1/sqrt(512)) / rowsum
    }
    __syncthreads();

    #pragma unroll
    for (int mt = 0; mt < 2; mt++)
        #pragma unroll
        for (int half = 0; half < 2; half++) {
            int rloc = m0 + mt * 16 + lq + half * 8;
            long gRow = (long)bz * NSEQ + rowBase + rloc;
            const float nrm = rsh[rloc];
            #pragma unroll
            for (int nt = 0; nt < 8; nt++) {
                int col = colBase + n0 + nt * 8 + lr * 2;
                float2 f = __ldcs((const float2*)&feat[gRow * CDIM + col]);
                float2 o;
                o.x = fmaf(acc[mt][nt][half * 2 + 0], nrm, f.x);
                o.y = fmaf(acc[mt][nt][half * 2 + 1], nrm, f.y);
                __stcs((float2*)&out[gRow * CDIM + col], o);
            }
        }
}

// ---------------------------------------------------------------------------
#define SMEM_NT_BYTES (4 * NT_TILE_B)                 // 73728
#define SMEM_PV_BYTES (2 * NT_TILE_B + 2 * NN_TILE_B) // 71680

extern "C" void kernel_launch(void* const* d_in, const int* in_sizes, int n_in,
                              void* d_out, int out_size)
{
    const float* feat = (const float*)d_in[0];
    const float* wq   = (const float*)d_in[1];
    const float* bq   = (const float*)d_in[2];
    const float* wk   = (const float*)d_in[3];
    const float* bk   = (const float*)d_in[4];
    const float* wv   = (const float*)d_in[5];
    const float* bv   = (const float*)d_in[6];
    float* out = (float*)d_out;

    cudaFuncSetAttribute(qkv_bf16,    cudaFuncAttributeMaxDynamicSharedMemorySize, SMEM_NT_BYTES);
    cudaFuncSetAttribute(scores_bf16, cudaFuncAttributeMaxDynamicSharedMemorySize, SMEM_NT_BYTES);
    cudaFuncSetAttribute(pv_bf16,     cudaFuncAttributeMaxDynamicSharedMemorySize, SMEM_PV_BYTES);

    // Convert all inputs to bf16 (single launch)
    conv_all<<<dim3(CONV_BLOCKS), 256>>>((const float4*)feat, (const float4*)wq,
                                         (const float4*)wk, (const float4*)wv);

    // QKV: 4 col blocks (512/128), 128 row blocks (16384/128), z = {q,k,v}
    qkv_bf16<<<dim3(4, 128, 3), 256, SMEM_NT_BYTES>>>(bq, bk, bv);
    // Scores + exp + row partial sums: 16x16 blocks, 8 batches
    scores_bf16<<<dim3(16, 16, 8), 256, SMEM_NT_BYTES>>>();
    // PV + residual + normalize: 4 col blocks, 16 row blocks, 8 batches
    pv_bf16<<<dim3(4, 16, 8), 256, SMEM_PV_BYTES>>>(feat, out);
}

// round 15
// speedup vs baseline: 1.5811x; 1.0646x over previous
#include <cuda_runtime.h>
#include <cuda_bf16.h>
#include <cstdint>

#define BATCH 8
#define NSEQ  2048
#define CDIM  512

// ---------------------------------------------------------------------------
// Scratch (__device__ globals per allocation-free rule)
// ---------------------------------------------------------------------------
__device__ __align__(16) __nv_bfloat16 g_fb[BATCH * NSEQ * CDIM];      // feat bf16
__device__ __align__(16) __nv_bfloat16 g_wb[3 * CDIM * CDIM];          // wq,wk,wv bf16
__device__ __align__(16) __nv_bfloat16 g_qb[BATCH * NSEQ * CDIM];
__device__ __align__(16) __nv_bfloat16 g_kb[BATCH * NSEQ * CDIM];
__device__ __align__(16) __nv_bfloat16 g_vb[BATCH * NSEQ * CDIM];      // natural [m][d]
__device__ __align__(16) __nv_bfloat16 g_s[(size_t)BATCH * NSEQ * NSEQ];  // exp(S-30)
// 32 partial sums per row: 16 col-blocks x 2 n-warps.
__device__ __align__(16) float g_spart[BATCH * NSEQ * 32];
// Per-batch count of completed scores CTAs (256 each). Zeroed by conv_all.
__device__ int g_done[BATCH];

// ---------------------------------------------------------------------------
// Helpers
// ---------------------------------------------------------------------------
__device__ __forceinline__ uint32_t smem_to_u32(const void* p) {
    uint32_t a;
    asm("{ .reg .u64 t; cvta.to.shared.u64 t, %1; cvt.u32.u64 %0, t; }" : "=r"(a) : "l"(p));
    return a;
}

__device__ __forceinline__ void cp_async16(uint32_t saddr, const void* gptr) {
    asm volatile("cp.async.cg.shared.global [%0], [%1], 16;" :: "r"(saddr), "l"(gptr));
}
#define CP_COMMIT() asm volatile("cp.async.commit_group;" ::: "memory")
#define CP_WAIT0()  asm volatile("cp.async.wait_group 0;" ::: "memory")

__device__ __forceinline__ void ldsm4(uint32_t r[4], uint32_t addr) {
    asm volatile("ldmatrix.sync.aligned.m8n8.x4.shared.b16 {%0,%1,%2,%3}, [%4];"
        : "=r"(r[0]), "=r"(r[1]), "=r"(r[2]), "=r"(r[3]) : "r"(addr));
}
__device__ __forceinline__ void ldsm4t(uint32_t r[4], uint32_t addr) {
    asm volatile("ldmatrix.sync.aligned.m8n8.x4.trans.shared.b16 {%0,%1,%2,%3}, [%4];"
        : "=r"(r[0]), "=r"(r[1]), "=r"(r[2]), "=r"(r[3]) : "r"(addr));
}

__device__ __forceinline__ void mma_bf16(float c[4], const uint32_t a[4], const uint32_t b[2]) {
    asm volatile(
        "mma.sync.aligned.m16n8k16.row.col.f32.bf16.bf16.f32 "
        "{%0,%1,%2,%3}, {%4,%5,%6,%7}, {%8,%9}, {%0,%1,%2,%3};"
        : "+f"(c[0]), "+f"(c[1]), "+f"(c[2]), "+f"(c[3])
        : "r"(a[0]), "r"(a[1]), "r"(a[2]), "r"(a[3]), "r"(b[0]), "r"(b[1]));
}

__device__ __forceinline__ uint32_t packbf(float x, float y) {
    __nv_bfloat162 h = __floats2bfloat162_rn(x, y);
    return *reinterpret_cast<uint32_t*>(&h);
}

// ---------------------------------------------------------------------------
// SMEM tile layouts (bf16, padded rows so ldmatrix 16B units hit distinct banks)
//   NT tile: 128 rows x 64 k-bf16, row stride 72 bf16 = 144 B -> 18432 B
//   NN tile:  64 k-rows x 128 n-bf16, row stride 136 bf16 = 272 B -> 17408 B
// ---------------------------------------------------------------------------
#define NT_TILE_B 18432
#define NN_TILE_B 17408

__device__ __forceinline__ void load_ntb(const __nv_bfloat16* __restrict__ g, long ld,
                                         int rowBase, int kt, uint32_t sbase, int tid) {
    #pragma unroll
    for (int i = 0; i < 4; i++) {
        int idx = i * 256 + tid;      // 1024 chunks of 16B
        int r = idx >> 3, f8 = idx & 7;
        cp_async16(sbase + (uint32_t)(r * 144 + f8 * 16),
                   g + (long)(rowBase + r) * ld + kt + f8 * 8);
    }
}

__device__ __forceinline__ void load_nnb(const __nv_bfloat16* __restrict__ g, long ld,
                                         int colBase, int kt, uint32_t sbase, int tid) {
    #pragma unroll
    for (int i = 0; i < 4; i++) {
        int idx = i * 256 + tid;
        int r = idx >> 4, c8 = idx & 15;
        cp_async16(sbase + (uint32_t)(r * 272 + c8 * 16),
                   g + (long)(kt + r) * ld + colBase + c8 * 8);
    }
}

// One 64-k slab, warp tile 32x64. A from NT tile; B NT (BNN=0) or NN+trans (BNN=1).
template<int BNN>
__device__ __forceinline__ void slab_bf16(uint32_t aBase, uint32_t bBase,
                                          float acc[2][8][4], int m0, int n0, int lane) {
    uint32_t aOff[2], bOff[4];
    #pragma unroll
    for (int mt = 0; mt < 2; mt++)
        aOff[mt] = (uint32_t)((m0 + mt * 16 + (lane & 15)) * 144 + ((lane & 16) ? 16 : 0));
    #pragma unroll
    for (int nt2 = 0; nt2 < 4; nt2++) {
        if (BNN)
            bOff[nt2] = (uint32_t)(((lane & 7) + ((lane & 8) ? 8 : 0)) * 272
                        + (n0 + nt2 * 16) * 2 + ((lane & 16) ? 16 : 0));
        else
            bOff[nt2] = (uint32_t)((n0 + nt2 * 16 + (lane & 7) + ((lane & 16) ? 8 : 0)) * 144
                        + ((lane & 8) ? 16 : 0));
    }
    #pragma unroll
    for (int kk = 0; kk < 4; kk++) {
        uint32_t a[2][4];
        ldsm4(a[0], aBase + aOff[0] + kk * 32);
        ldsm4(a[1], aBase + aOff[1] + kk * 32);
        uint32_t b[4][4];
        #pragma unroll
        for (int nt2 = 0; nt2 < 4; nt2++) {
            if (BNN) ldsm4t(b[nt2], bBase + bOff[nt2] + kk * 16 * 272);
            else     ldsm4 (b[nt2], bBase + bOff[nt2] + kk * 32);
        }
        #pragma unroll
        for (int mt = 0; mt < 2; mt++)
            #pragma unroll
            for (int nt2 = 0; nt2 < 4; nt2++) {
                mma_bf16(acc[mt][nt2 * 2 + 0], a[mt], &b[nt2][0]);
                mma_bf16(acc[mt][nt2 * 2 + 1], a[mt], &b[nt2][2]);
            }
    }
}

// ---------------------------------------------------------------------------
// Combined convert kernel (f32 -> bf16): feat then wq/wk/wv. Also zeroes the
// per-batch dependency counters (block 0).
// ---------------------------------------------------------------------------
#define FEAT_F4 (BATCH * NSEQ * CDIM / 4)          // 2097152
#define W_F4    (CDIM * CDIM / 4)                  // 65536
#define CONV_BLOCKS ((FEAT_F4 + 3 * W_F4) / 256)   // 8960

__global__ __launch_bounds__(256) void conv_all(const float4* __restrict__ feat,
                                                const float4* __restrict__ wq,
                                                const float4* __restrict__ wk,
                                                const float4* __restrict__ wv) {
    if (blockIdx.x == 0 && threadIdx.x < BATCH) g_done[threadIdx.x] = 0;
    int idx = blockIdx.x * 256 + threadIdx.x;
    const float4* src;
    uint2* dst;
    int off;
    if (idx < FEAT_F4) {
        src = feat;             dst = (uint2*)g_fb; off = idx;
    } else if (idx < FEAT_F4 + W_F4) {
        src = wq;  dst = (uint2*)g_wb;              off = idx - FEAT_F4;
    } else if (idx < FEAT_F4 + 2 * W_F4) {
        src = wk;  dst = (uint2*)g_wb + W_F4;       off = idx - FEAT_F4 - W_F4;
    } else {
        src = wv;  dst = (uint2*)g_wb + 2 * W_F4;   off = idx - FEAT_F4 - 2 * W_F4;
    }
    float4 v = src[off];
    uint2 o;
    o.x = packbf(v.x, v.y);
    o.y = packbf(v.z, v.w);
    dst[off] = o;
}

// ---------------------------------------------------------------------------
// Kernel 1: QKV projections (NT). CTA 128x128, 256 thr, 2-stage pipeline.
// ---------------------------------------------------------------------------
__global__ __launch_bounds__(256, 2) void qkv_bf16(
    const float* __restrict__ bq, const float* __restrict__ bk,
    const float* __restrict__ bv)
{
    extern __shared__ char sm[];
    uint32_t sb = smem_to_u32(sm);
    const int tid = threadIdx.x;
    const int wid = tid >> 5, lane = tid & 31;
    const int lq = lane >> 2, lr = lane & 3;
    const int m0 = (wid >> 1) * 32, n0 = (wid & 1) * 64;
    const int z = blockIdx.z;
    const __nv_bfloat16* W = g_wb + (long)z * CDIM * CDIM;
    const float* bias = (z == 0) ? bq : (z == 1) ? bk : bv;
    __nv_bfloat16* out = (z == 0) ? g_qb : (z == 1) ? g_kb : g_vb;

    const int rowBase = blockIdx.y * 128;
    const int colBase = blockIdx.x * 128;

    uint32_t aAddr[2] = { sb, sb + NT_TILE_B };
    uint32_t bAddr[2] = { sb + 2 * NT_TILE_B, sb + 3 * NT_TILE_B };

    float acc[2][8][4] = {};

    load_ntb(g_fb, CDIM, rowBase, 0, aAddr[0], tid);
    load_ntb(W,    CDIM, colBase, 0, bAddr[0], tid);
    CP_COMMIT(); CP_WAIT0();
    __syncthreads();

    const int nslab = CDIM / 64;
    for (int s = 0; s < nslab; s++) {
        int cur = s & 1;
        if (s + 1 < nslab) {
            int nxt = cur ^ 1;
            load_ntb(g_fb, CDIM, rowBase, (s + 1) * 64, aAddr[nxt], tid);
            load_ntb(W,    CDIM, colBase, (s + 1) * 64, bAddr[nxt], tid);
            CP_COMMIT();
        }
        slab_bf16<0>(aAddr[cur], bAddr[cur], acc, m0, n0, lane);
        if (s + 1 < nslab) CP_WAIT0();
        __syncthreads();
    }

    #pragma unroll
    for (int mt = 0; mt < 2; mt++)
        #pragma unroll
        for (int half = 0; half < 2; half++) {
            int row = rowBase + m0 + mt * 16 + lq + half * 8;
            #pragma unroll
            for (int nt = 0; nt < 8; nt++) {
                int col = colBase + n0 + nt * 8 + lr * 2;
                uint32_t p = packbf(acc[mt][nt][half * 2 + 0] + bias[col + 0],
                                    acc[mt][nt][half * 2 + 1] + bias[col + 1]);
                *(uint32_t*)&out[(long)row * CDIM + col] = p;
            }
        }
}

// ---------------------------------------------------------------------------
// Kernel 2: FUSED scores + pv. Grid = 2048 scores CTAs (bids 0..2047) then
// 512 pv CTAs (bids 2048..2559). Scores CTA of batch bz arrives on g_done[bz];
// pv CTA of batch bz waits for all 256 arrivals. CTAs dispatch in bid order
// and scores depends on nothing -> guaranteed progress.
// ---------------------------------------------------------------------------
#define SCORES_CTAS 2048

__global__ __launch_bounds__(256, 2) void sp_fused(const float* __restrict__ feat,
                                                   float* __restrict__ out)
{
    extern __shared__ char sm[];
    uint32_t sb = smem_to_u32(sm);
    const int tid = threadIdx.x;
    const int wid = tid >> 5, lane = tid & 31;
    const int lq = lane >> 2, lr = lane & 3;
    const int m0 = (wid >> 1) * 32, n0 = (wid & 1) * 64;
    const int bid = blockIdx.x;

    if (bid < SCORES_CTAS) {
        // ---------------- scores role ----------------
        const int bz = bid >> 8;
        const int cib = bid & 255;
        const int colBase = (cib & 15) * 128;
        const int rowBase = (cib >> 4) * 128;

        const __nv_bfloat16* Aq = g_qb + (long)bz * NSEQ * CDIM;
        const __nv_bfloat16* Bk = g_kb + (long)bz * NSEQ * CDIM;
        __nv_bfloat16* outS = g_s + (size_t)bz * NSEQ * NSEQ;

        uint32_t aAddr[2] = { sb, sb + NT_TILE_B };
        uint32_t bAddr[2] = { sb + 2 * NT_TILE_B, sb + 3 * NT_TILE_B };

        float acc[2][8][4] = {};

        load_ntb(Aq, CDIM, rowBase, 0, aAddr[0], tid);
        load_ntb(Bk, CDIM, colBase, 0, bAddr[0], tid);
        CP_COMMIT(); CP_WAIT0();
        __syncthreads();

        const int nslab = CDIM / 64;
        for (int s = 0; s < nslab; s++) {
            int cur = s & 1;
            if (s + 1 < nslab) {
                int nxt = cur ^ 1;
                load_ntb(Aq, CDIM, rowBase, (s + 1) * 64, aAddr[nxt], tid);
                load_ntb(Bk, CDIM, colBase, (s + 1) * 64, bAddr[nxt], tid);
                CP_COMMIT();
            }
            slab_bf16<0>(aAddr[cur], bAddr[cur], acc, m0, n0, lane);
            if (s + 1 < nslab) CP_WAIT0();
            __syncthreads();
        }

        #pragma unroll
        for (int mt = 0; mt < 2; mt++)
            #pragma unroll
            for (int half = 0; half < 2; half++) {
                int row = rowBase + m0 + mt * 16 + lq + half * 8;
                float rp = 0.f;
                #pragma unroll
                for (int nt = 0; nt < 8; nt++) {
                    int col = colBase + n0 + nt * 8 + lr * 2;
                    float e0 = __expf(acc[mt][nt][half * 2 + 0] - 30.0f);
                    float e1 = __expf(acc[mt][nt][half * 2 + 1] - 30.0f);
                    rp += e0 + e1;
                    *(uint32_t*)&outS[(size_t)row * NSEQ + col] = packbf(e0, e1);
                }
                rp += __shfl_xor_sync(0xffffffffu, rp, 1);
                rp += __shfl_xor_sync(0xffffffffu, rp, 2);
                if (lr == 0) {
                    int part = (cib & 15) * 2 + (n0 >> 6);   // 0..31, unique per warp
                    g_spart[((size_t)(bz * NSEQ) + row) * 32 + part] = rp;
                }
            }

        // Signal completion (after all stores are visible device-wide).
        __syncthreads();
        __threadfence();
        if (tid == 0) atomicAdd(&g_done[bz], 1);
    } else {
        // ---------------- pv role ----------------
        const int p = bid - SCORES_CTAS;
        const int bz = p >> 6;
        const int cta = p & 63;
        const int colBase = (cta & 3) * 128;
        const int rowBase = (cta >> 2) * 128;

        // Wait for all 256 scores CTAs of this batch.
        if (tid == 0) {
            volatile int* dp = (volatile int*)&g_done[bz];
            while (*dp < 256) { }
        }
        __syncthreads();

        const __nv_bfloat16* Ap = g_s + (size_t)bz * NSEQ * NSEQ;
        const __nv_bfloat16* Bv = g_vb + (long)bz * NSEQ * CDIM;

        uint32_t aAddr[2] = { sb, sb + NT_TILE_B };
        uint32_t bAddr[2] = { sb + 2 * NT_TILE_B, sb + 2 * NT_TILE_B + NN_TILE_B };

        float acc[2][8][4] = {};

        load_ntb(Ap, NSEQ, rowBase, 0, aAddr[0], tid);
        load_nnb(Bv, CDIM, colBase, 0, bAddr[0], tid);
        CP_COMMIT(); CP_WAIT0();
        __syncthreads();

        const int nslab = NSEQ / 64;
        for (int s = 0; s < nslab; s++) {
            int cur = s & 1;
            if (s + 1 < nslab) {
                int nxt = cur ^ 1;
                load_ntb(Ap, NSEQ, rowBase, (s + 1) * 64, aAddr[nxt], tid);
                load_nnb(Bv, CDIM, colBase, (s + 1) * 64, bAddr[nxt], tid);
                CP_COMMIT();
            }
            slab_bf16<1>(aAddr[cur], bAddr[cur], acc, m0, n0, lane);
            if (s + 1 < nslab) CP_WAIT0();
            __syncthreads();
        }

        // Gather row normalizers (L2-coherent loads; written by other SMs).
        float* rsh = (float*)sm;
        if (tid < 128) {
            const float4* pp = (const float4*)(g_spart + ((size_t)(bz * NSEQ) + rowBase + tid) * 32);
            float ssum = 0.f;
            #pragma unroll
            for (int i = 0; i < 8; i++) {
                float4 v = __ldcg(&pp[i]);
                ssum += (v.x + v.y) + (v.z + v.w);
            }
            rsh[tid] = 0.044194173824159216f / ssum;   // (1/sqrt(512)) / rowsum
        }
        __syncthreads();

        #pragma unroll
        for (int mt = 0; mt < 2; mt++)
            #pragma unroll
            for (int half = 0; half < 2; half++) {
                int rloc = m0 + mt * 16 + lq + half * 8;
                long gRow = (long)bz * NSEQ + rowBase + rloc;
                const float nrm = rsh[rloc];
                #pragma unroll
                for (int nt = 0; nt < 8; nt++) {
                    int col = colBase + n0 + nt * 8 + lr * 2;
                    float2 f = *(const float2*)&feat[gRow * CDIM + col];
                    float2 o;
                    o.x = fmaf(acc[mt][nt][half * 2 + 0], nrm, f.x);
                    o.y = fmaf(acc[mt][nt][half * 2 + 1], nrm, f.y);
                    *(float2*)&out[gRow * CDIM + col] = o;
                }
            }
    }
}

// ---------------------------------------------------------------------------
#define SMEM_NT_BYTES (4 * NT_TILE_B)                 // 73728 (max of both roles)

extern "C" void kernel_launch(void* const* d_in, const int* in_sizes, int n_in,
                              void* d_out, int out_size)
{
    const float* feat = (const float*)d_in[0];
    const float* wq   = (const float*)d_in[1];
    const float* bq   = (const float*)d_in[2];
    const float* wk   = (const float*)d_in[3];
    const float* bk   = (const float*)d_in[4];
    const float* wv   = (const float*)d_in[5];
    const float* bv   = (const float*)d_in[6];
    float* out = (float*)d_out;

    cudaFuncSetAttribute(qkv_bf16, cudaFuncAttributeMaxDynamicSharedMemorySize, SMEM_NT_BYTES);
    cudaFuncSetAttribute(sp_fused, cudaFuncAttributeMaxDynamicSharedMemorySize, SMEM_NT_BYTES);

    // Convert inputs to bf16 + zero dependency counters (single launch)
    conv_all<<<dim3(CONV_BLOCKS), 256>>>((const float4*)feat, (const float4*)wq,
                                         (const float4*)wk, (const float4*)wv);

    // QKV: 4 col blocks (512/128), 128 row blocks (16384/128), z = {q,k,v}
    qkv_bf16<<<dim3(4, 128, 3), 256, SMEM_NT_BYTES>>>(bq, bk, bv);

    // Fused scores (+exp +partials) and pv (+residual +normalize):
    // 2048 scores CTAs followed by 512 pv CTAs with device-side dependency.
    sp_fused<<<dim3(SCORES_CTAS + 512), 256, SMEM_NT_BYTES>>>(feat, out);
}

// round 16
// speedup vs baseline: 1.6069x; 1.0163x over previous
#include <cuda_runtime.h>
#include <cuda_bf16.h>
#include <cstdint>

#define BATCH 8
#define NSEQ  2048
#define CDIM  512

// ---------------------------------------------------------------------------
// Scratch (__device__ globals per allocation-free rule)
// ---------------------------------------------------------------------------
__device__ __align__(16) __nv_bfloat16 g_fb[BATCH * NSEQ * CDIM];      // feat bf16
__device__ __align__(16) __nv_bfloat16 g_wb[3 * CDIM * CDIM];          // wq,wk,wv bf16
__device__ __align__(16) __nv_bfloat16 g_qb[BATCH * NSEQ * CDIM];
__device__ __align__(16) __nv_bfloat16 g_kb[BATCH * NSEQ * CDIM];
__device__ __align__(16) __nv_bfloat16 g_vb[BATCH * NSEQ * CDIM];      // natural [m][d]
__device__ __align__(16) __nv_bfloat16 g_s[(size_t)BATCH * NSEQ * NSEQ];  // exp(S-30)
// 32 partial sums per row: 16 col-blocks x 2 n-warps.
__device__ __align__(16) float g_spart[BATCH * NSEQ * 32];
// Dependency counters (zeroed by conv_all):
//   [z*128 + rb]  : qkv rowblock rb of matrix z complete (target 4), z in {0,1}
//   [384 + bz]    : V CTAs of batch bz complete (target 64)
//   [392 + bz]    : scores CTAs of batch bz complete (target 256)
#define CNT_V   384
#define CNT_S   392
#define CNT_N   400
__device__ int g_cnt[CNT_N];

// ---------------------------------------------------------------------------
// Helpers
// ---------------------------------------------------------------------------
__device__ __forceinline__ uint32_t smem_to_u32(const void* p) {
    uint32_t a;
    asm("{ .reg .u64 t; cvta.to.shared.u64 t, %1; cvt.u32.u64 %0, t; }" : "=r"(a) : "l"(p));
    return a;
}

__device__ __forceinline__ void cp_async16(uint32_t saddr, const void* gptr) {
    asm volatile("cp.async.cg.shared.global [%0], [%1], 16;" :: "r"(saddr), "l"(gptr));
}
#define CP_COMMIT() asm volatile("cp.async.commit_group;" ::: "memory")
#define CP_WAIT0()  asm volatile("cp.async.wait_group 0;" ::: "memory")

__device__ __forceinline__ void ldsm4(uint32_t r[4], uint32_t addr) {
    asm volatile("ldmatrix.sync.aligned.m8n8.x4.shared.b16 {%0,%1,%2,%3}, [%4];"
        : "=r"(r[0]), "=r"(r[1]), "=r"(r[2]), "=r"(r[3]) : "r"(addr));
}
__device__ __forceinline__ void ldsm4t(uint32_t r[4], uint32_t addr) {
    asm volatile("ldmatrix.sync.aligned.m8n8.x4.trans.shared.b16 {%0,%1,%2,%3}, [%4];"
        : "=r"(r[0]), "=r"(r[1]), "=r"(r[2]), "=r"(r[3]) : "r"(addr));
}

__device__ __forceinline__ void mma_bf16(float c[4], const uint32_t a[4], const uint32_t b[2]) {
    asm volatile(
        "mma.sync.aligned.m16n8k16.row.col.f32.bf16.bf16.f32 "
        "{%0,%1,%2,%3}, {%4,%5,%6,%7}, {%8,%9}, {%0,%1,%2,%3};"
        : "+f"(c[0]), "+f"(c[1]), "+f"(c[2]), "+f"(c[3])
        : "r"(a[0]), "r"(a[1]), "r"(a[2]), "r"(a[3]), "r"(b[0]), "r"(b[1]));
}

__device__ __forceinline__ uint32_t packbf(float x, float y) {
    __nv_bfloat162 h = __floats2bfloat162_rn(x, y);
    return *reinterpret_cast<uint32_t*>(&h);
}

// ---------------------------------------------------------------------------
// SMEM tile layouts (bf16, padded rows so ldmatrix 16B units hit distinct banks)
//   NT tile: 128 rows x 64 k-bf16, row stride 72 bf16 = 144 B -> 18432 B
//   NN tile:  64 k-rows x 128 n-bf16, row stride 136 bf16 = 272 B -> 17408 B
// ---------------------------------------------------------------------------
#define NT_TILE_B 18432
#define NN_TILE_B 17408

__device__ __forceinline__ void load_ntb(const __nv_bfloat16* __restrict__ g, long ld,
                                         int rowBase, int kt, uint32_t sbase, int tid) {
    #pragma unroll
    for (int i = 0; i < 4; i++) {
        int idx = i * 256 + tid;      // 1024 chunks of 16B
        int r = idx >> 3, f8 = idx & 7;
        cp_async16(sbase + (uint32_t)(r * 144 + f8 * 16),
                   g + (long)(rowBase + r) * ld + kt + f8 * 8);
    }
}

__device__ __forceinline__ void load_nnb(const __nv_bfloat16* __restrict__ g, long ld,
                                         int colBase, int kt, uint32_t sbase, int tid) {
    #pragma unroll
    for (int i = 0; i < 4; i++) {
        int idx = i * 256 + tid;
        int r = idx >> 4, c8 = idx & 15;
        cp_async16(sbase + (uint32_t)(r * 272 + c8 * 16),
                   g + (long)(kt + r) * ld + colBase + c8 * 8);
    }
}

// One 64-k slab, warp tile 32x64. A from NT tile; B NT (BNN=0) or NN+trans (BNN=1).
template<int BNN>
__device__ __forceinline__ void slab_bf16(uint32_t aBase, uint32_t bBase,
                                          float acc[2][8][4], int m0, int n0, int lane) {
    uint32_t aOff[2], bOff[4];
    #pragma unroll
    for (int mt = 0; mt < 2; mt++)
        aOff[mt] = (uint32_t)((m0 + mt * 16 + (lane & 15)) * 144 + ((lane & 16) ? 16 : 0));
    #pragma unroll
    for (int nt2 = 0; nt2 < 4; nt2++) {
        if (BNN)
            bOff[nt2] = (uint32_t)(((lane & 7) + ((lane & 8) ? 8 : 0)) * 272
                        + (n0 + nt2 * 16) * 2 + ((lane & 16) ? 16 : 0));
        else
            bOff[nt2] = (uint32_t)((n0 + nt2 * 16 + (lane & 7) + ((lane & 16) ? 8 : 0)) * 144
                        + ((lane & 8) ? 16 : 0));
    }
    #pragma unroll
    for (int kk = 0; kk < 4; kk++) {
        uint32_t a[2][4];
        ldsm4(a[0], aBase + aOff[0] + kk * 32);
        ldsm4(a[1], aBase + aOff[1] + kk * 32);
        uint32_t b[4][4];
        #pragma unroll
        for (int nt2 = 0; nt2 < 4; nt2++) {
            if (BNN) ldsm4t(b[nt2], bBase + bOff[nt2] + kk * 16 * 272);
            else     ldsm4 (b[nt2], bBase + bOff[nt2] + kk * 32);
        }
        #pragma unroll
        for (int mt = 0; mt < 2; mt++)
            #pragma unroll
            for (int nt2 = 0; nt2 < 4; nt2++) {
                mma_bf16(acc[mt][nt2 * 2 + 0], a[mt], &b[nt2][0]);
                mma_bf16(acc[mt][nt2 * 2 + 1], a[mt], &b[nt2][2]);
            }
    }
}

// ---------------------------------------------------------------------------
// Combined convert kernel (f32 -> bf16): feat then wq/wk/wv. Block 0 also
// zeroes the dependency counters.
// ---------------------------------------------------------------------------
#define FEAT_F4 (BATCH * NSEQ * CDIM / 4)          // 2097152
#define W_F4    (CDIM * CDIM / 4)                  // 65536
#define CONV_BLOCKS ((FEAT_F4 + 3 * W_F4) / 256)   // 8960

__global__ __launch_bounds__(256) void conv_all(const float4* __restrict__ feat,
                                                const float4* __restrict__ wq,
                                                const float4* __restrict__ wk,
                                                const float4* __restrict__ wv) {
    if (blockIdx.x == 0) {
        for (int i = threadIdx.x; i < CNT_N; i += 256) g_cnt[i] = 0;
    }
    int idx = blockIdx.x * 256 + threadIdx.x;
    const float4* src;
    uint2* dst;
    int off;
    if (idx < FEAT_F4) {
        src = feat;             dst = (uint2*)g_fb; off = idx;
    } else if (idx < FEAT_F4 + W_F4) {
        src = wq;  dst = (uint2*)g_wb;              off = idx - FEAT_F4;
    } else if (idx < FEAT_F4 + 2 * W_F4) {
        src = wk;  dst = (uint2*)g_wb + W_F4;       off = idx - FEAT_F4 - W_F4;
    } else {
        src = wv;  dst = (uint2*)g_wb + 2 * W_F4;   off = idx - FEAT_F4 - 2 * W_F4;
    }
    float4 v = src[off];
    uint2 o;
    o.x = packbf(v.x, v.y);
    o.y = packbf(v.z, v.w);
    dst[off] = o;
}

// ---------------------------------------------------------------------------
// Mega kernel: qkv (bids 0..1535) + scores (1536..3583) + pv (3584..4095).
// qkv bid layout: bid = rb*12 + z*4 + cb  (rowblock-major, z interleaved) so
// early rowblocks of ALL of Q/K/V finish first -> scores of batch 0 can start
// while qkv is ~12% done. All dependencies point to strictly lower bids.
// ---------------------------------------------------------------------------
#define QKV_CTAS    1536
#define SCORES_CTAS 2048

__global__ __launch_bounds__(256, 2) void mega(const float* __restrict__ feat,
                                               float* __restrict__ out,
                                               const float* __restrict__ bq,
                                               const float* __restrict__ bk,
                                               const float* __restrict__ bv)
{
    extern __shared__ char sm[];
    uint32_t sb = smem_to_u32(sm);
    const int tid = threadIdx.x;
    const int wid = tid >> 5, lane = tid & 31;
    const int lq = lane >> 2, lr = lane & 3;
    const int m0 = (wid >> 1) * 32, n0 = (wid & 1) * 64;
    const int bid = blockIdx.x;

    if (bid < QKV_CTAS) {
        // ---------------- qkv role ----------------
        const int rb = bid / 12;
        const int rem = bid - rb * 12;
        const int z = rem >> 2;
        const int cb = rem & 3;
        const int rowBase = rb * 128;
        const int colBase = cb * 128;

        const __nv_bfloat16* W = g_wb + (long)z * CDIM * CDIM;
        const float* bias = (z == 0) ? bq : (z == 1) ? bk : bv;
        __nv_bfloat16* outM = (z == 0) ? g_qb : (z == 1) ? g_kb : g_vb;

        uint32_t aAddr[2] = { sb, sb + NT_TILE_B };
        uint32_t bAddr[2] = { sb + 2 * NT_TILE_B, sb + 3 * NT_TILE_B };

        float acc[2][8][4] = {};

        load_ntb(g_fb, CDIM, rowBase, 0, aAddr[0], tid);
        load_ntb(W,    CDIM, colBase, 0, bAddr[0], tid);
        CP_COMMIT(); CP_WAIT0();
        __syncthreads();

        const int nslab = CDIM / 64;
        for (int s = 0; s < nslab; s++) {
            int cur = s & 1;
            if (s + 1 < nslab) {
                int nxt = cur ^ 1;
                load_ntb(g_fb, CDIM, rowBase, (s + 1) * 64, aAddr[nxt], tid);
                load_ntb(W,    CDIM, colBase, (s + 1) * 64, bAddr[nxt], tid);
                CP_COMMIT();
            }
            slab_bf16<0>(aAddr[cur], bAddr[cur], acc, m0, n0, lane);
            if (s + 1 < nslab) CP_WAIT0();
            __syncthreads();
        }

        #pragma unroll
        for (int mt = 0; mt < 2; mt++)
            #pragma unroll
            for (int half = 0; half < 2; half++) {
                int row = rowBase + m0 + mt * 16 + lq + half * 8;
                #pragma unroll
                for (int nt = 0; nt < 8; nt++) {
                    int col = colBase + n0 + nt * 8 + lr * 2;
                    uint32_t p = packbf(acc[mt][nt][half * 2 + 0] + bias[col + 0],
                                        acc[mt][nt][half * 2 + 1] + bias[col + 1]);
                    *(uint32_t*)&outM[(long)row * CDIM + col] = p;
                }
            }

        __syncthreads();
        __threadfence();
        if (tid == 0) {
            if (z < 2) atomicAdd(&g_cnt[z * 128 + rb], 1);
            else       atomicAdd(&g_cnt[CNT_V + (rb >> 4)], 1);
        }
    } else if (bid < QKV_CTAS + SCORES_CTAS) {
        // ---------------- scores role ----------------
        const int sbid = bid - QKV_CTAS;
        const int bz = sbid >> 8;
        const int cib = sbid & 255;
        const int colBase = (cib & 15) * 128;
        const int rowBase = (cib >> 4) * 128;

        // Wait for Q rowblock and K rowblock of this tile.
        if (tid == 0) {
            volatile int* q = (volatile int*)&g_cnt[0 * 128 + bz * 16 + (rowBase >> 7)];
            volatile int* k = (volatile int*)&g_cnt[1 * 128 + bz * 16 + (colBase >> 7)];
            while (*q < 4) { }
            while (*k < 4) { }
        }
        __syncthreads();

        const __nv_bfloat16* Aq = g_qb + (long)bz * NSEQ * CDIM;
        const __nv_bfloat16* Bk = g_kb + (long)bz * NSEQ * CDIM;
        __nv_bfloat16* outS = g_s + (size_t)bz * NSEQ * NSEQ;

        uint32_t aAddr[2] = { sb, sb + NT_TILE_B };
        uint32_t bAddr[2] = { sb + 2 * NT_TILE_B, sb + 3 * NT_TILE_B };

        float acc[2][8][4] = {};

        load_ntb(Aq, CDIM, rowBase, 0, aAddr[0], tid);
        load_ntb(Bk, CDIM, colBase, 0, bAddr[0], tid);
        CP_COMMIT(); CP_WAIT0();
        __syncthreads();

        const int nslab = CDIM / 64;
        for (int s = 0; s < nslab; s++) {
            int cur = s & 1;
            if (s + 1 < nslab) {
                int nxt = cur ^ 1;
                load_ntb(Aq, CDIM, rowBase, (s + 1) * 64, aAddr[nxt], tid);
                load_ntb(Bk, CDIM, colBase, (s + 1) * 64, bAddr[nxt], tid);
                CP_COMMIT();
            }
            slab_bf16<0>(aAddr[cur], bAddr[cur], acc, m0, n0, lane);
            if (s + 1 < nslab) CP_WAIT0();
            __syncthreads();
        }

        #pragma unroll
        for (int mt = 0; mt < 2; mt++)
            #pragma unroll
            for (int half = 0; half < 2; half++) {
                int row = rowBase + m0 + mt * 16 + lq + half * 8;
                float rp = 0.f;
                #pragma unroll
                for (int nt = 0; nt < 8; nt++) {
                    int col = colBase + n0 + nt * 8 + lr * 2;
                    float e0 = __expf(acc[mt][nt][half * 2 + 0] - 30.0f);
                    float e1 = __expf(acc[mt][nt][half * 2 + 1] - 30.0f);
                    rp += e0 + e1;
                    *(uint32_t*)&outS[(size_t)row * NSEQ + col] = packbf(e0, e1);
                }
                rp += __shfl_xor_sync(0xffffffffu, rp, 1);
                rp += __shfl_xor_sync(0xffffffffu, rp, 2);
                if (lr == 0) {
                    int part = (cib & 15) * 2 + (n0 >> 6);   // 0..31, unique per warp
                    g_spart[((size_t)(bz * NSEQ) + row) * 32 + part] = rp;
                }
            }

        __syncthreads();
        __threadfence();
        if (tid == 0) atomicAdd(&g_cnt[CNT_S + bz], 1);
    } else {
        // ---------------- pv role ----------------
        const int p = bid - QKV_CTAS - SCORES_CTAS;
        const int bz = p >> 6;
        const int cta = p & 63;
        const int colBase = (cta & 3) * 128;
        const int rowBase = (cta >> 2) * 128;

        // Wait for all scores of this batch and all V CTAs of this batch.
        if (tid == 0) {
            volatile int* sdone = (volatile int*)&g_cnt[CNT_S + bz];
            volatile int* vdone = (volatile int*)&g_cnt[CNT_V + bz];
            while (*vdone < 64) { }
            while (*sdone < 256) { }
        }
        __syncthreads();

        const __nv_bfloat16* Ap = g_s + (size_t)bz * NSEQ * NSEQ;
        const __nv_bfloat16* Bv = g_vb + (long)bz * NSEQ * CDIM;

        uint32_t aAddr[2] = { sb, sb + NT_TILE_B };
        uint32_t bAddr[2] = { sb + 2 * NT_TILE_B, sb + 2 * NT_TILE_B + NN_TILE_B };

        float acc[2][8][4] = {};

        load_ntb(Ap, NSEQ, rowBase, 0, aAddr[0], tid);
        load_nnb(Bv, CDIM, colBase, 0, bAddr[0], tid);
        CP_COMMIT(); CP_WAIT0();
        __syncthreads();

        const int nslab = NSEQ / 64;
        for (int s = 0; s < nslab; s++) {
            int cur = s & 1;
            if (s + 1 < nslab) {
                int nxt = cur ^ 1;
                load_ntb(Ap, NSEQ, rowBase, (s + 1) * 64, aAddr[nxt], tid);
                load_nnb(Bv, CDIM, colBase, (s + 1) * 64, bAddr[nxt], tid);
                CP_COMMIT();
            }
            slab_bf16<1>(aAddr[cur], bAddr[cur], acc, m0, n0, lane);
            if (s + 1 < nslab) CP_WAIT0();
            __syncthreads();
        }

        // Gather row normalizers (L2-coherent loads; written by other SMs).
        float* rsh = (float*)sm;
        if (tid < 128) {
            const float4* pp = (const float4*)(g_spart + ((size_t)(bz * NSEQ) + rowBase + tid) * 32);
            float ssum = 0.f;
            #pragma unroll
            for (int i = 0; i < 8; i++) {
                float4 v = __ldcg(&pp[i]);
                ssum += (v.x + v.y) + (v.z + v.w);
            }
            rsh[tid] = 0.044194173824159216f / ssum;   // (1/sqrt(512)) / rowsum
        }
        __syncthreads();

        #pragma unroll
        for (int mt = 0; mt < 2; mt++)
            #pragma unroll
            for (int half = 0; half < 2; half++) {
                int rloc = m0 + mt * 16 + lq + half * 8;
                long gRow = (long)bz * NSEQ + rowBase + rloc;
                const float nrm = rsh[rloc];
                #pragma unroll
                for (int nt = 0; nt < 8; nt++) {
                    int col = colBase + n0 + nt * 8 + lr * 2;
                    float2 f = *(const float2*)&feat[gRow * CDIM + col];
                    float2 o;
                    o.x = fmaf(acc[mt][nt][half * 2 + 0], nrm, f.x);
                    o.y = fmaf(acc[mt][nt][half * 2 + 1], nrm, f.y);
                    *(float2*)&out[gRow * CDIM + col] = o;
                }
            }
    }
}

// ---------------------------------------------------------------------------
#define SMEM_NT_BYTES (4 * NT_TILE_B)                 // 73728 (max of all roles)

extern "C" void kernel_launch(void* const* d_in, const int* in_sizes, int n_in,
                              void* d_out, int out_size)
{
    const float* feat = (const float*)d_in[0];
    const float* wq   = (const float*)d_in[1];
    const float* bq   = (const float*)d_in[2];
    const float* wk   = (const float*)d_in[3];
    const float* bk   = (const float*)d_in[4];
    const float* wv   = (const float*)d_in[5];
    const float* bv   = (const float*)d_in[6];
    float* out = (float*)d_out;

    cudaFuncSetAttribute(mega, cudaFuncAttributeMaxDynamicSharedMemorySize, SMEM_NT_BYTES);

    // Convert inputs to bf16 + zero dependency counters (single launch)
    conv_all<<<dim3(CONV_BLOCKS), 256>>>((const float4*)feat, (const float4*)wq,
                                         (const float4*)wk, (const float4*)wv);

    // Fused qkv + scores + pv with device-side dependencies.
    mega<<<dim3(QKV_CTAS + SCORES_CTAS + 512), 256, SMEM_NT_BYTES>>>(feat, out,
                                                                     bq, bk, bv);
}